// round 12
// baseline (speedup 1.0000x reference)
#include <cuda_runtime.h>
#include <cuda_bf16.h>
#include <cstdint>

#define N_NODES_MAX 100000
#define IN_C 300
#define OUT_C 200
#define E_MAX 1600000
#define ETOT_MAX (E_MAX + N_NODES_MAX)
#define NEG_SLOPE 0.2f

#define KP0 320
#define KP1 224
#define NPAD 256          // padded N rows for weight tiles (2 x BN=128)
#define SKP 40            // smem k pitch (halves)
#define TS (128 * SKP)    // halves per tile array
#define GEMM_SMEM (2 * 4 * TS * 2)  // 2 stages * 4 arrays * TS halves * 2B

// ---------------- scratch ----------------
__device__ float g_h[(size_t)N_NODES_MAX * OUT_C];
__device__ float g_as[N_NODES_MAX];
__device__ float g_ad[N_NODES_MAX];
__device__ float g_s[N_NODES_MAX];
__device__ int   g_idx64;
// CSR
__device__ int   g_deg[N_NODES_MAX];
__device__ int   g_off[N_NODES_MAX + 1];
__device__ int   g_cur[N_NODES_MAX];
__device__ int   g_bsum[256];
__device__ int   g_boff[257];
__device__ int   g_csr_src[ETOT_MAX];
__device__ int2  g_pair[ETOT_MAX];    // {src, float_bits(exp_e)} packed for passC
// bf16 split buffers
__device__ __nv_bfloat16 g_ahi[(size_t)N_NODES_MAX * KP1];
__device__ __nv_bfloat16 g_alo[(size_t)N_NODES_MAX * KP1];
__device__ __nv_bfloat16 g_whi0[(size_t)NPAD * KP0];
__device__ __nv_bfloat16 g_wlo0[(size_t)NPAD * KP0];
__device__ __nv_bfloat16 g_whi1[(size_t)NPAD * KP1];
__device__ __nv_bfloat16 g_wlo1[(size_t)NPAD * KP1];

// ---------------- helpers ----------------
__device__ __forceinline__ int edge_at(const void* ei, int is64, long long pos) {
    if (is64) return (int)((const long long*)ei)[pos];
    return ((const int*)ei)[pos];
}

__device__ __forceinline__ uint32_t smem_u32(const void* p) {
    return (uint32_t)__cvta_generic_to_shared(p);
}

__device__ __forceinline__ void cp16(uint32_t dst, const void* src, bool pred) {
    int sz = pred ? 16 : 0;
    asm volatile("cp.async.cg.shared.global [%0], [%1], 16, %2;"
                 :: "r"(dst), "l"(src), "r"(sz));
}

#define CP_COMMIT() asm volatile("cp.async.commit_group;")
#define CP_WAIT(N)  asm volatile("cp.async.wait_group %0;" :: "n"(N))

#define LDSM_X4(r0, r1, r2, r3, addr)                                        \
    asm volatile("ldmatrix.sync.aligned.m8n8.x4.shared.b16 {%0,%1,%2,%3}, [%4];" \
                 : "=r"(r0), "=r"(r1), "=r"(r2), "=r"(r3) : "r"(addr))

#define MMA_BF16(d, a, b)                                                    \
    asm volatile("mma.sync.aligned.m16n8k16.row.col.f32.bf16.bf16.f32 "      \
                 "{%0,%1,%2,%3},{%4,%5,%6,%7},{%8,%9},{%0,%1,%2,%3};"        \
                 : "+f"(d[0]), "+f"(d[1]), "+f"(d[2]), "+f"(d[3])            \
                 : "r"(a[0]), "r"(a[1]), "r"(a[2]), "r"(a[3]),               \
                   "r"(b[0]), "r"(b[1]))

__device__ __forceinline__ void bf16_split(float v, __nv_bfloat16& hi, __nv_bfloat16& lo) {
    hi = __float2bfloat16(v);
    lo = __float2bfloat16(v - __bfloat162float(hi));
}

__device__ __forceinline__ void split4(float4 v, uint2& uh, uint2& ul) {
    __nv_bfloat162 h01 = __floats2bfloat162_rn(v.x, v.y);
    __nv_bfloat162 h23 = __floats2bfloat162_rn(v.z, v.w);
    float2 f01 = __bfloat1622float2(h01);
    float2 f23 = __bfloat1622float2(h23);
    __nv_bfloat162 l01 = __floats2bfloat162_rn(v.x - f01.x, v.y - f01.y);
    __nv_bfloat162 l23 = __floats2bfloat162_rn(v.z - f23.x, v.w - f23.y);
    uh.x = *(uint32_t*)&h01; uh.y = *(uint32_t*)&h23;
    ul.x = *(uint32_t*)&l01; ul.y = *(uint32_t*)&l23;
}

__global__ void probe_kernel(const int* ei) {
    if (threadIdx.x == 0 && blockIdx.x == 0) {
        int is64 = 1;
        #pragma unroll
        for (int i = 1; i < 32; i += 2)
            if (ei[i] != 0) { is64 = 0; break; }
        g_idx64 = is64;
    }
}

__global__ void zero_asad_kernel(int n) {
    int i = blockIdx.x * blockDim.x + threadIdx.x;
    if (i < n) { g_as[i] = 0.f; g_ad[i] = 0.f; }
}

// ---------------- CSR build --------------------------------------------------
__global__ void zero_deg_kernel(int n) {
    int i = blockIdx.x * blockDim.x + threadIdx.x;
    if (i < n) g_deg[i] = 0;
}

__global__ void hist_kernel(const void* __restrict__ ei, int E, int Etot) {
    int i = blockIdx.x * blockDim.x + threadIdx.x;
    if (i >= Etot) return;
    int is64 = g_idx64;
    int dst = (i < E) ? edge_at(ei, is64, (long long)E + i) : (i - E);
    atomicAdd(&g_deg[dst], 1);
}

__global__ __launch_bounds__(1024) void scan1_kernel(int n) {
    __shared__ int sh[1024];
    int t = threadIdx.x;
    int i = blockIdx.x * 1024 + t;
    int v = (i < n) ? g_deg[i] : 0;
    sh[t] = v;
    __syncthreads();
    #pragma unroll
    for (int o = 1; o < 1024; o <<= 1) {
        int u = (t >= o) ? sh[t - o] : 0;
        __syncthreads();
        sh[t] += u;
        __syncthreads();
    }
    if (i < n) g_off[i] = sh[t] - v;
    if (t == 1023) g_bsum[blockIdx.x] = sh[1023];
}

__global__ __launch_bounds__(128) void scan2_kernel(int nb) {
    __shared__ int sh[128];
    int t = threadIdx.x;
    int v = (t < nb) ? g_bsum[t] : 0;
    sh[t] = v;
    __syncthreads();
    #pragma unroll
    for (int o = 1; o < 128; o <<= 1) {
        int u = (t >= o) ? sh[t - o] : 0;
        __syncthreads();
        sh[t] += u;
        __syncthreads();
    }
    g_boff[t] = sh[t] - v;
    if (t == 127) g_boff[128] = sh[127];
}

__global__ void scan3_kernel(int n) {
    int i = blockIdx.x * blockDim.x + threadIdx.x;
    if (i < n) {
        int o = g_off[i] + g_boff[i >> 10];
        g_off[i] = o;
        g_cur[i] = o;
    }
    if (i == 0) g_off[n] = g_boff[128];
}

__global__ void fill_kernel(const void* __restrict__ ei, int E, int Etot) {
    int i = blockIdx.x * blockDim.x + threadIdx.x;
    if (i >= Etot) return;
    int is64 = g_idx64;
    int src, dst;
    if (i < E) {
        src = edge_at(ei, is64, i);
        dst = edge_at(ei, is64, (long long)E + i);
    } else {
        src = dst = i - E;
    }
    int pos = atomicAdd(&g_cur[dst], 1);
    g_csr_src[pos] = src;
}

// ---------------- split W -----------------------------------------------------
__global__ void split_w_kernel(const float* __restrict__ W, int K, int KP,
                               __nv_bfloat16* __restrict__ Wh,
                               __nv_bfloat16* __restrict__ Wl) {
    int idx = blockIdx.x * blockDim.x + threadIdx.x;
    if (idx >= NPAD * KP) return;
    int k = idx % KP;
    int n = idx / KP;
    float v = (k < K && n < OUT_C) ? W[(size_t)k * OUT_C + n] : 0.f;
    __nv_bfloat16 hi, lo;
    bf16_split(v, hi, lo);
    Wh[idx] = hi;
    Wl[idx] = lo;
}

// ---------------- tensor-core GEMM + fused alpha epilogue --------------------
// BM=128, BN=128, 8 warps (2m x 4n), warp tile 64x32. 2 CTAs/SM enforced.
// AFP32: A loaded as fp32 (layer-1 x), split to bf16 hi/lo in-register (sync LDG).
// !AFP32: A loaded from g_ahi/g_alo via cp.async (layer 2).
template<bool AFP32>
__global__ __launch_bounds__(256, 2)
void gemm_tc_kernel(int M, int ldaA, int Kin, int ldaB, int kblocks,
                    const float* __restrict__ Afp,
                    const __nv_bfloat16* __restrict__ Wh,
                    const __nv_bfloat16* __restrict__ Wl,
                    const float* __restrict__ a_src,
                    const float* __restrict__ a_dst) {
    extern __shared__ __nv_bfloat16 smem[];

    int tid = threadIdx.x;
    int lane = tid & 31, warp = tid >> 5;
    int wm = warp & 1, wn = warp >> 1;
    int bm = blockIdx.x * 128;
    int n0 = blockIdx.y * 128;

    float acc[4][4][4];
    #pragma unroll
    for (int i = 0; i < 4; i++)
        #pragma unroll
        for (int j = 0; j < 4; j++)
            #pragma unroll
            for (int q = 0; q < 4; q++) acc[i][j][q] = 0.f;

    int a_r = lane & 15, a_c = (lane >> 4) << 3;
    int b_r = (lane & 7) + ((lane >> 4) << 3);
    int b_c = ((lane >> 3) & 1) << 3;

    auto load_stage = [&](int kb, int s) {
        __nv_bfloat16* sAh = smem + s * 4 * TS;
        __nv_bfloat16* sAl = sAh + TS;
        __nv_bfloat16* sBh = sAl + TS;
        __nv_bfloat16* sBl = sBh + TS;
        if (AFP32) {
            // A: 128 rows x 32 floats = 1024 float4 over 256 threads (sync LDG)
            #pragma unroll
            for (int i = 0; i < 4; i++) {
                int idx = tid + i * 256;
                int row = idx >> 3, qf = idx & 7;
                int gk = kb * 32 + qf * 4;
                float4 f = make_float4(0.f, 0.f, 0.f, 0.f);
                if ((bm + row) < M && (gk + 4) <= Kin)
                    f = *(const float4*)(Afp + (size_t)(bm + row) * ldaA + gk);
                uint2 uh, ul;
                split4(f, uh, ul);
                *(uint2*)(sAh + row * SKP + qf * 4) = uh;
                *(uint2*)(sAl + row * SKP + qf * 4) = ul;
            }
        } else {
            #pragma unroll
            for (int i = 0; i < 2; i++) {
                int idx = tid + i * 256;
                int row = idx >> 2, q = idx & 3;
                bool vA = (bm + row) < M;
                int rA = vA ? (bm + row) : 0;
                size_t offA = (size_t)rA * ldaA + kb * 32 + q * 8;
                cp16(smem_u32(sAh + row * SKP + q * 8), g_ahi + offA, vA);
                cp16(smem_u32(sAl + row * SKP + q * 8), g_alo + offA, vA);
            }
        }
        #pragma unroll
        for (int i = 0; i < 2; i++) {
            int idx = tid + i * 256;
            int row = idx >> 2, q = idx & 3;
            size_t offB = (size_t)(n0 + row) * ldaB + kb * 32 + q * 8;
            cp16(smem_u32(sBh + row * SKP + q * 8), Wh + offB, true);
            cp16(smem_u32(sBl + row * SKP + q * 8), Wl + offB, true);
        }
        CP_COMMIT();
    };

    load_stage(0, 0);

    for (int kb = 0; kb < kblocks; kb++) {
        if (kb + 1 < kblocks) {
            load_stage(kb + 1, (kb + 1) & 1);
            CP_WAIT(1);
        } else {
            CP_WAIT(0);
        }
        __syncthreads();

        int s = kb & 1;
        __nv_bfloat16* sAh = smem + s * 4 * TS;
        __nv_bfloat16* sAl = sAh + TS;
        __nv_bfloat16* sBh = sAl + TS;
        __nv_bfloat16* sBl = sBh + TS;

        #pragma unroll
        for (int ks = 0; ks < 2; ks++) {
            int kh = ks * 16;
            uint32_t ah[4][4], al[4][4], bh[4][2], bl[4][2];
            #pragma unroll
            for (int mi = 0; mi < 4; mi++) {
                int row = wm * 64 + mi * 16 + a_r;
                uint32_t ad = smem_u32(sAh + row * SKP + kh + a_c);
                LDSM_X4(ah[mi][0], ah[mi][1], ah[mi][2], ah[mi][3], ad);
                ad = smem_u32(sAl + row * SKP + kh + a_c);
                LDSM_X4(al[mi][0], al[mi][1], al[mi][2], al[mi][3], ad);
            }
            #pragma unroll
            for (int nj = 0; nj < 2; nj++) {
                int row = wn * 32 + nj * 16 + b_r;
                uint32_t ad = smem_u32(sBh + row * SKP + kh + b_c);
                LDSM_X4(bh[2 * nj][0], bh[2 * nj][1], bh[2 * nj + 1][0], bh[2 * nj + 1][1], ad);
                ad = smem_u32(sBl + row * SKP + kh + b_c);
                LDSM_X4(bl[2 * nj][0], bl[2 * nj][1], bl[2 * nj + 1][0], bl[2 * nj + 1][1], ad);
            }
            #pragma unroll
            for (int mi = 0; mi < 4; mi++)
                #pragma unroll
                for (int ni = 0; ni < 4; ni++) {
                    MMA_BF16(acc[mi][ni], ah[mi], bh[ni]);
                    MMA_BF16(acc[mi][ni], ah[mi], bl[ni]);
                    MMA_BF16(acc[mi][ni], al[mi], bh[ni]);
                }
        }
        __syncthreads();
    }

    float vs0[4], vs1[4], vd0[4], vd1[4];
    #pragma unroll
    for (int ni = 0; ni < 4; ni++) {
        int c = n0 + wn * 32 + ni * 8 + ((lane & 3) << 1);
        vs0[ni] = (c < OUT_C) ? __ldg(a_src + c) : 0.f;
        vs1[ni] = (c + 1 < OUT_C) ? __ldg(a_src + c + 1) : 0.f;
        vd0[ni] = (c < OUT_C) ? __ldg(a_dst + c) : 0.f;
        vd1[ni] = (c + 1 < OUT_C) ? __ldg(a_dst + c + 1) : 0.f;
    }

    #pragma unroll
    for (int mi = 0; mi < 4; mi++) {
        int r = bm + wm * 64 + mi * 16 + (lane >> 2);
        #pragma unroll
        for (int ni = 0; ni < 4; ni++) {
            int c = n0 + wn * 32 + ni * 8 + ((lane & 3) << 1);
            if (c >= OUT_C) continue;
            if (r < M)
                *(float2*)(g_h + (size_t)r * OUT_C + c) =
                    make_float2(acc[mi][ni][0], acc[mi][ni][1]);
            if (r + 8 < M)
                *(float2*)(g_h + (size_t)(r + 8) * OUT_C + c) =
                    make_float2(acc[mi][ni][2], acc[mi][ni][3]);
        }
        float ps0 = 0.f, pd0 = 0.f, ps1 = 0.f, pd1 = 0.f;
        #pragma unroll
        for (int ni = 0; ni < 4; ni++) {
            ps0 += acc[mi][ni][0] * vs0[ni] + acc[mi][ni][1] * vs1[ni];
            pd0 += acc[mi][ni][0] * vd0[ni] + acc[mi][ni][1] * vd1[ni];
            ps1 += acc[mi][ni][2] * vs0[ni] + acc[mi][ni][3] * vs1[ni];
            pd1 += acc[mi][ni][2] * vd0[ni] + acc[mi][ni][3] * vd1[ni];
        }
        #pragma unroll
        for (int o = 1; o <= 2; o <<= 1) {
            ps0 += __shfl_xor_sync(0xffffffffu, ps0, o);
            pd0 += __shfl_xor_sync(0xffffffffu, pd0, o);
            ps1 += __shfl_xor_sync(0xffffffffu, ps1, o);
            pd1 += __shfl_xor_sync(0xffffffffu, pd1, o);
        }
        if ((lane & 3) == 0) {
            if (r < M) { atomicAdd(&g_as[r], ps0); atomicAdd(&g_ad[r], pd0); }
            if (r + 8 < M) { atomicAdd(&g_as[r + 8], ps1); atomicAdd(&g_ad[r + 8], pd1); }
        }
    }
}

// ---------------- fused passAB: warp per dst; e + exp + segment sum ----------
// Writes packed {src, exp_e} records for passC.
__global__ void passAB_kernel(int n) {
    int w = (int)((blockIdx.x * (size_t)blockDim.x + threadIdx.x) >> 5);
    int lane = threadIdx.x & 31;
    if (w >= n) return;
    int off = g_off[w], deg = g_deg[w];
    float ad = __ldg(&g_ad[w]);
    float s = 0.f;
    for (int i = lane; i < deg; i += 32) {
        int src = __ldg(&g_csr_src[off + i]);
        float e = __ldg(&g_as[src]) + ad;
        e = (e > 0.f) ? e : NEG_SLOPE * e;
        float ex = __expf(e);
        g_pair[off + i] = make_int2(src, __float_as_int(ex));
        s += ex;
    }
    #pragma unroll
    for (int o = 16; o; o >>= 1) s += __shfl_xor_sync(0xffffffffu, s, o);
    if (lane == 0) g_s[w] = __frcp_rn(s);
}

// ---------------- passC layer 1: aggregate + bias + relu -> bf16 hi/lo -------
__global__ __launch_bounds__(896)
void passC_bf16_kernel(int n, const float* __restrict__ bias) {
    int t = blockIdx.x * 896 + threadIdx.x;
    int d = t / 56;
    int c = t % 56;
    if (d >= n) return;
    size_t base = (size_t)d * KP1 + c * 4;
    if (c >= 50) {
        *(uint2*)(g_ahi + base) = make_uint2(0, 0);
        *(uint2*)(g_alo + base) = make_uint2(0, 0);
        return;
    }
    float rs = __ldg(&g_s[d]);
    int off = g_off[d], deg = g_deg[d];
    float4 acc = __ldg((const float4*)bias + c);
    const float4* h4 = (const float4*)g_h;
    for (int j = 0; j < deg; j++) {
        int2 p = __ldg(&g_pair[off + j]);
        float a = __int_as_float(p.y) * rs;
        float4 v = __ldg(h4 + (size_t)p.x * (OUT_C / 4) + c);
        acc.x = fmaf(a, v.x, acc.x);
        acc.y = fmaf(a, v.y, acc.y);
        acc.z = fmaf(a, v.z, acc.z);
        acc.w = fmaf(a, v.w, acc.w);
    }
    acc.x = fmaxf(acc.x, 0.f); acc.y = fmaxf(acc.y, 0.f);
    acc.z = fmaxf(acc.z, 0.f); acc.w = fmaxf(acc.w, 0.f);
    uint2 uh, ul;
    split4(acc, uh, ul);
    *(uint2*)(g_ahi + base) = uh;
    *(uint2*)(g_alo + base) = ul;
}

// ---------------- passC layer 2: aggregate + bias + relu -> fp32 out ---------
__global__ __launch_bounds__(800)
void passC_f32_kernel(int n, float* __restrict__ out,
                      const float* __restrict__ bias) {
    int t = blockIdx.x * 800 + threadIdx.x;
    int d = t / 50;
    int c = t % 50;
    if (d >= n) return;
    float rs = __ldg(&g_s[d]);
    int off = g_off[d], deg = g_deg[d];
    float4 acc = __ldg((const float4*)bias + c);
    const float4* h4 = (const float4*)g_h;
    for (int j = 0; j < deg; j++) {
        int2 p = __ldg(&g_pair[off + j]);
        float a = __int_as_float(p.y) * rs;
        float4 v = __ldg(h4 + (size_t)p.x * (OUT_C / 4) + c);
        acc.x = fmaf(a, v.x, acc.x);
        acc.y = fmaf(a, v.y, acc.y);
        acc.z = fmaf(a, v.z, acc.z);
        acc.w = fmaf(a, v.w, acc.w);
    }
    acc.x = fmaxf(acc.x, 0.f); acc.y = fmaxf(acc.y, 0.f);
    acc.z = fmaxf(acc.z, 0.f); acc.w = fmaxf(acc.w, 0.f);
    ((float4*)out)[(size_t)d * (OUT_C / 4) + c] = acc;
}

// ---------------- launch (single stream, no forking) -------------------------
extern "C" void kernel_launch(void* const* d_in, const int* in_sizes, int n_in,
                              void* d_out, int out_size) {
    const float* x      = (const float*)d_in[0];
    const float* W0     = (const float*)d_in[1];
    const float* a_src0 = (const float*)d_in[2];
    const float* a_dst0 = (const float*)d_in[3];
    const float* b0     = (const float*)d_in[4];
    const float* W1     = (const float*)d_in[5];
    const float* a_src1 = (const float*)d_in[6];
    const float* a_dst1 = (const float*)d_in[7];
    const float* b1     = (const float*)d_in[8];
    const void*  ei     = d_in[9];

    int n    = in_sizes[0] / IN_C;   // 100000
    int E    = in_sizes[9] / 2;      // 1600000
    int Etot = E + n;

    cudaFuncSetAttribute(gemm_tc_kernel<true>,
                         cudaFuncAttributeMaxDynamicSharedMemorySize, GEMM_SMEM);
    cudaFuncSetAttribute(gemm_tc_kernel<false>,
                         cudaFuncAttributeMaxDynamicSharedMemorySize, GEMM_SMEM);

    dim3 gemm_grid((n + 127) / 128, 2);
    int node_blocks  = (n + 255) / 256;
    int edge_blocks  = (Etot + 511) / 512;
    int scan_blocks  = (n + 1023) / 1024;
    int warp_blocks  = (int)(((long long)n * 32 + 255) / 256);
    int aggC1_blocks = (int)(((long long)n * 56 + 895) / 896);
    int aggC2_blocks = (int)(((long long)n * 50 + 799) / 800);

    // ----- layer 1 front (gemm is 4th launch -> ncu capture) -----
    zero_asad_kernel<<<node_blocks, 256>>>(n);
    probe_kernel<<<1, 32>>>((const int*)ei);
    split_w_kernel<<<(NPAD * KP0 + 255) / 256, 256>>>(W0, IN_C, KP0,
                                                      g_whi0, g_wlo0);
    gemm_tc_kernel<true><<<gemm_grid, 256, GEMM_SMEM>>>(
        n, IN_C, IN_C, KP0, KP0 / 32, x, g_whi0, g_wlo0, a_src0, a_dst0);

    // ----- CSR build -----
    zero_deg_kernel<<<node_blocks, 256>>>(n);
    hist_kernel<<<edge_blocks, 512>>>(ei, E, Etot);
    scan1_kernel<<<scan_blocks, 1024>>>(n);
    scan2_kernel<<<1, 128>>>(scan_blocks);
    scan3_kernel<<<node_blocks, 256>>>(n);
    fill_kernel<<<edge_blocks, 512>>>(ei, E, Etot);

    // ----- layer 1 back -----
    passAB_kernel<<<warp_blocks, 256>>>(n);
    passC_bf16_kernel<<<aggC1_blocks, 896>>>(n, b0);

    // ----- layer 2 -----
    zero_asad_kernel<<<node_blocks, 256>>>(n);
    split_w_kernel<<<(NPAD * KP1 + 255) / 256, 256>>>(W1, OUT_C, KP1,
                                                      g_whi1, g_wlo1);
    gemm_tc_kernel<false><<<gemm_grid, 256, GEMM_SMEM>>>(
        n, KP1, OUT_C, KP1, KP1 / 32, nullptr, g_whi1, g_wlo1, a_src1, a_dst1);
    passAB_kernel<<<warp_blocks, 256>>>(n);
    passC_f32_kernel<<<aggC2_blocks, 800>>>(n, (float*)d_out, b1);
}

// round 13
// speedup vs baseline: 5.4202x; 5.4202x over previous
#include <cuda_runtime.h>
#include <cuda_bf16.h>
#include <cstdint>

#define N_NODES_MAX 100000
#define IN_C 300
#define OUT_C 200
#define E_MAX 1600000
#define ETOT_MAX (E_MAX + N_NODES_MAX)
#define NEG_SLOPE 0.2f

#define KP0 320
#define KP1 224
#define NPAD 256          // padded N for weight tiles (2 x BN=128)
#define SKP 40            // smem k pitch (halves)
#define TS (128 * SKP)    // halves per tile array
#define GEMM_SMEM (2 * 4 * TS * 2)  // 2 stages * 4 arrays * TS halves * 2B

// ---------------- scratch ----------------
__device__ float g_h[(size_t)N_NODES_MAX * OUT_C];
__device__ float g_as[N_NODES_MAX];
__device__ float g_ad[N_NODES_MAX];
__device__ float g_s[N_NODES_MAX];
__device__ int   g_idx64;
// CSR
__device__ int   g_deg[N_NODES_MAX];
__device__ int   g_off[N_NODES_MAX + 1];
__device__ int   g_cur[N_NODES_MAX];
__device__ int   g_bsum[256];
__device__ int   g_boff[257];
__device__ int   g_csr_src[ETOT_MAX];
__device__ float g_e_csr[ETOT_MAX];
// bf16 split buffers (layer-2 A written by passC; weights per layer)
__device__ __nv_bfloat16 g_ahi[(size_t)N_NODES_MAX * KP1];
__device__ __nv_bfloat16 g_alo[(size_t)N_NODES_MAX * KP1];
__device__ __nv_bfloat16 g_whi[(size_t)NPAD * KP0];
__device__ __nv_bfloat16 g_wlo[(size_t)NPAD * KP0];

// ---------------- helpers ----------------
__device__ __forceinline__ int edge_at(const void* ei, int is64, long long pos) {
    if (is64) return (int)((const long long*)ei)[pos];
    return ((const int*)ei)[pos];
}

__device__ __forceinline__ uint32_t smem_u32(const void* p) {
    return (uint32_t)__cvta_generic_to_shared(p);
}

__device__ __forceinline__ void cp16(uint32_t dst, const void* src, bool pred) {
    int sz = pred ? 16 : 0;
    asm volatile("cp.async.cg.shared.global [%0], [%1], 16, %2;"
                 :: "r"(dst), "l"(src), "r"(sz));
}

#define CP_COMMIT() asm volatile("cp.async.commit_group;")
#define CP_WAIT(N)  asm volatile("cp.async.wait_group %0;" :: "n"(N))

#define LDSM_X4(r0, r1, r2, r3, addr)                                        \
    asm volatile("ldmatrix.sync.aligned.m8n8.x4.shared.b16 {%0,%1,%2,%3}, [%4];" \
                 : "=r"(r0), "=r"(r1), "=r"(r2), "=r"(r3) : "r"(addr))

#define MMA_BF16(d, a, b)                                                    \
    asm volatile("mma.sync.aligned.m16n8k16.row.col.f32.bf16.bf16.f32 "      \
                 "{%0,%1,%2,%3},{%4,%5,%6,%7},{%8,%9},{%0,%1,%2,%3};"        \
                 : "+f"(d[0]), "+f"(d[1]), "+f"(d[2]), "+f"(d[3])            \
                 : "r"(a[0]), "r"(a[1]), "r"(a[2]), "r"(a[3]),               \
                   "r"(b[0]), "r"(b[1]))

__device__ __forceinline__ void bf16_split(float v, __nv_bfloat16& hi, __nv_bfloat16& lo) {
    hi = __float2bfloat16(v);
    lo = __float2bfloat16(v - __bfloat162float(hi));
}

// split a float4 into packed hi (uint2) and lo (uint2) bf16x4
__device__ __forceinline__ void split4(float4 v, uint2& uh, uint2& ul) {
    __nv_bfloat162 h01 = __floats2bfloat162_rn(v.x, v.y);
    __nv_bfloat162 h23 = __floats2bfloat162_rn(v.z, v.w);
    float2 f01 = __bfloat1622float2(h01);
    float2 f23 = __bfloat1622float2(h23);
    __nv_bfloat162 l01 = __floats2bfloat162_rn(v.x - f01.x, v.y - f01.y);
    __nv_bfloat162 l23 = __floats2bfloat162_rn(v.z - f23.x, v.w - f23.y);
    uh.x = *(uint32_t*)&h01; uh.y = *(uint32_t*)&h23;
    ul.x = *(uint32_t*)&l01; ul.y = *(uint32_t*)&l23;
}

__global__ void probe_kernel(const int* ei) {
    if (threadIdx.x == 0 && blockIdx.x == 0) {
        int is64 = 1;
        #pragma unroll
        for (int i = 1; i < 32; i += 2)
            if (ei[i] != 0) { is64 = 0; break; }
        g_idx64 = is64;
    }
}

__global__ void zero_asad_kernel(int n) {
    int i = blockIdx.x * blockDim.x + threadIdx.x;
    if (i < n) { g_as[i] = 0.f; g_ad[i] = 0.f; }
}

// ---------------- CSR build --------------------------------------------------
__global__ void zero_deg_kernel(int n) {
    int i = blockIdx.x * blockDim.x + threadIdx.x;
    if (i < n) g_deg[i] = 0;
}

__global__ void hist_kernel(const void* __restrict__ ei, int E, int Etot) {
    int i = blockIdx.x * blockDim.x + threadIdx.x;
    if (i >= Etot) return;
    int is64 = g_idx64;
    int dst = (i < E) ? edge_at(ei, is64, (long long)E + i) : (i - E);
    atomicAdd(&g_deg[dst], 1);
}

__global__ __launch_bounds__(1024) void scan1_kernel(int n) {
    __shared__ int sh[1024];
    int t = threadIdx.x;
    int i = blockIdx.x * 1024 + t;
    int v = (i < n) ? g_deg[i] : 0;
    sh[t] = v;
    __syncthreads();
    #pragma unroll
    for (int o = 1; o < 1024; o <<= 1) {
        int u = (t >= o) ? sh[t - o] : 0;
        __syncthreads();
        sh[t] += u;
        __syncthreads();
    }
    if (i < n) g_off[i] = sh[t] - v;
    if (t == 1023) g_bsum[blockIdx.x] = sh[1023];
}

__global__ __launch_bounds__(128) void scan2_kernel(int nb) {
    __shared__ int sh[128];
    int t = threadIdx.x;
    int v = (t < nb) ? g_bsum[t] : 0;
    sh[t] = v;
    __syncthreads();
    #pragma unroll
    for (int o = 1; o < 128; o <<= 1) {
        int u = (t >= o) ? sh[t - o] : 0;
        __syncthreads();
        sh[t] += u;
        __syncthreads();
    }
    g_boff[t] = sh[t] - v;
    if (t == 127) g_boff[128] = sh[127];
}

__global__ void scan3_kernel(int n) {
    int i = blockIdx.x * blockDim.x + threadIdx.x;
    if (i < n) {
        int o = g_off[i] + g_boff[i >> 10];
        g_off[i] = o;
        g_cur[i] = o;
    }
    if (i == 0) g_off[n] = g_boff[128];
}

__global__ void fill_kernel(const void* __restrict__ ei, int E, int Etot) {
    int i = blockIdx.x * blockDim.x + threadIdx.x;
    if (i >= Etot) return;
    int is64 = g_idx64;
    int src, dst;
    if (i < E) {
        src = edge_at(ei, is64, i);
        dst = edge_at(ei, is64, (long long)E + i);
    } else {
        src = dst = i - E;
    }
    int pos = atomicAdd(&g_cur[dst], 1);
    g_csr_src[pos] = src;
}

// ---------------- split W -----------------------------------------------------
__global__ void split_w_kernel(const float* __restrict__ W, int K, int KP) {
    int idx = blockIdx.x * blockDim.x + threadIdx.x;
    if (idx >= NPAD * KP) return;
    int k = idx % KP;
    int n = idx / KP;
    float v = (k < K && n < OUT_C) ? W[(size_t)k * OUT_C + n] : 0.f;
    __nv_bfloat16 hi, lo;
    bf16_split(v, hi, lo);
    g_whi[idx] = hi;
    g_wlo[idx] = lo;
}

// ---------------- tensor-core GEMM + fused alpha epilogue --------------------
// BM=128, BN=128, 8 warps (2m x 4n), warp tile 64x32. 2 CTAs/SM enforced.
// AFP32: A loaded as fp32 (layer-1 x), split to bf16 hi/lo in-register.
// !AFP32: A loaded from g_ahi/g_alo via cp.async (layer 2).
template<bool AFP32>
__global__ __launch_bounds__(256, 2)
void gemm_tc_kernel(int M, int ldaA, int Kin, int ldaB, int kblocks,
                    const float* __restrict__ Afp,
                    const float* __restrict__ a_src,
                    const float* __restrict__ a_dst) {
    extern __shared__ __nv_bfloat16 smem[];

    int tid = threadIdx.x;
    int lane = tid & 31, warp = tid >> 5;
    int wm = warp & 1, wn = warp >> 1;
    int bm = blockIdx.x * 128;
    int n0 = blockIdx.y * 128;

    float acc[4][4][4];
    #pragma unroll
    for (int i = 0; i < 4; i++)
        #pragma unroll
        for (int j = 0; j < 4; j++)
            #pragma unroll
            for (int q = 0; q < 4; q++) acc[i][j][q] = 0.f;

    int a_r = lane & 15, a_c = (lane >> 4) << 3;
    int b_r = (lane & 7) + ((lane >> 4) << 3);
    int b_c = ((lane >> 3) & 1) << 3;

    auto load_stage = [&](int kb, int s) {
        __nv_bfloat16* sAh = smem + s * 4 * TS;
        __nv_bfloat16* sAl = sAh + TS;
        __nv_bfloat16* sBh = sAl + TS;
        __nv_bfloat16* sBl = sBh + TS;
        if (AFP32) {
            // A: 128 rows x 32 floats = 1024 float4 loads over 256 threads
            #pragma unroll
            for (int i = 0; i < 4; i++) {
                int idx = tid + i * 256;
                int row = idx >> 3, qf = idx & 7;
                int gk = kb * 32 + qf * 4;
                float4 f = make_float4(0.f, 0.f, 0.f, 0.f);
                if ((bm + row) < M && (gk + 4) <= Kin)
                    f = *(const float4*)(Afp + (size_t)(bm + row) * ldaA + gk);
                uint2 uh, ul;
                split4(f, uh, ul);
                *(uint2*)(sAh + row * SKP + qf * 4) = uh;
                *(uint2*)(sAl + row * SKP + qf * 4) = ul;
            }
        } else {
            extern __device__ __nv_bfloat16 g_ahi[], g_alo[];
            #pragma unroll
            for (int i = 0; i < 2; i++) {
                int idx = tid + i * 256;
                int row = idx >> 2, q = idx & 3;
                bool vA = (bm + row) < M;
                int rA = vA ? (bm + row) : 0;
                size_t offA = (size_t)rA * ldaA + kb * 32 + q * 8;
                cp16(smem_u32(sAh + row * SKP + q * 8), g_ahi + offA, vA);
                cp16(smem_u32(sAl + row * SKP + q * 8), g_alo + offA, vA);
            }
        }
        #pragma unroll
        for (int i = 0; i < 2; i++) {
            int idx = tid + i * 256;
            int row = idx >> 2, q = idx & 3;
            size_t offB = (size_t)(n0 + row) * ldaB + kb * 32 + q * 8;
            cp16(smem_u32(sBh + row * SKP + q * 8), g_whi + offB, true);
            cp16(smem_u32(sBl + row * SKP + q * 8), g_wlo + offB, true);
        }
        CP_COMMIT();
    };

    load_stage(0, 0);

    for (int kb = 0; kb < kblocks; kb++) {
        if (kb + 1 < kblocks) {
            load_stage(kb + 1, (kb + 1) & 1);
            CP_WAIT(1);
        } else {
            CP_WAIT(0);
        }
        __syncthreads();

        int s = kb & 1;
        __nv_bfloat16* sAh = smem + s * 4 * TS;
        __nv_bfloat16* sAl = sAh + TS;
        __nv_bfloat16* sBh = sAl + TS;
        __nv_bfloat16* sBl = sBh + TS;

        #pragma unroll
        for (int ks = 0; ks < 2; ks++) {
            int kh = ks * 16;
            uint32_t ah[4][4], al[4][4], bh[4][2], bl[4][2];
            #pragma unroll
            for (int mi = 0; mi < 4; mi++) {
                int row = wm * 64 + mi * 16 + a_r;
                uint32_t ad = smem_u32(sAh + row * SKP + kh + a_c);
                LDSM_X4(ah[mi][0], ah[mi][1], ah[mi][2], ah[mi][3], ad);
                ad = smem_u32(sAl + row * SKP + kh + a_c);
                LDSM_X4(al[mi][0], al[mi][1], al[mi][2], al[mi][3], ad);
            }
            #pragma unroll
            for (int nj = 0; nj < 2; nj++) {
                int row = wn * 32 + nj * 16 + b_r;
                uint32_t ad = smem_u32(sBh + row * SKP + kh + b_c);
                LDSM_X4(bh[2 * nj][0], bh[2 * nj][1], bh[2 * nj + 1][0], bh[2 * nj + 1][1], ad);
                ad = smem_u32(sBl + row * SKP + kh + b_c);
                LDSM_X4(bl[2 * nj][0], bl[2 * nj][1], bl[2 * nj + 1][0], bl[2 * nj + 1][1], ad);
            }
            #pragma unroll
            for (int mi = 0; mi < 4; mi++)
                #pragma unroll
                for (int ni = 0; ni < 4; ni++) {
                    MMA_BF16(acc[mi][ni], ah[mi], bh[ni]);
                    MMA_BF16(acc[mi][ni], ah[mi], bl[ni]);
                    MMA_BF16(acc[mi][ni], al[mi], bh[ni]);
                }
        }
        __syncthreads();
    }

    float vs0[4], vs1[4], vd0[4], vd1[4];
    #pragma unroll
    for (int ni = 0; ni < 4; ni++) {
        int c = n0 + wn * 32 + ni * 8 + ((lane & 3) << 1);
        vs0[ni] = (c < OUT_C) ? __ldg(a_src + c) : 0.f;
        vs1[ni] = (c + 1 < OUT_C) ? __ldg(a_src + c + 1) : 0.f;
        vd0[ni] = (c < OUT_C) ? __ldg(a_dst + c) : 0.f;
        vd1[ni] = (c + 1 < OUT_C) ? __ldg(a_dst + c + 1) : 0.f;
    }

    #pragma unroll
    for (int mi = 0; mi < 4; mi++) {
        int r = bm + wm * 64 + mi * 16 + (lane >> 2);
        #pragma unroll
        for (int ni = 0; ni < 4; ni++) {
            int c = n0 + wn * 32 + ni * 8 + ((lane & 3) << 1);
            if (c >= OUT_C) continue;
            if (r < M)
                *(float2*)(g_h + (size_t)r * OUT_C + c) =
                    make_float2(acc[mi][ni][0], acc[mi][ni][1]);
            if (r + 8 < M)
                *(float2*)(g_h + (size_t)(r + 8) * OUT_C + c) =
                    make_float2(acc[mi][ni][2], acc[mi][ni][3]);
        }
        float ps0 = 0.f, pd0 = 0.f, ps1 = 0.f, pd1 = 0.f;
        #pragma unroll
        for (int ni = 0; ni < 4; ni++) {
            ps0 += acc[mi][ni][0] * vs0[ni] + acc[mi][ni][1] * vs1[ni];
            pd0 += acc[mi][ni][0] * vd0[ni] + acc[mi][ni][1] * vd1[ni];
            ps1 += acc[mi][ni][2] * vs0[ni] + acc[mi][ni][3] * vs1[ni];
            pd1 += acc[mi][ni][2] * vd0[ni] + acc[mi][ni][3] * vd1[ni];
        }
        #pragma unroll
        for (int o = 1; o <= 2; o <<= 1) {
            ps0 += __shfl_xor_sync(0xffffffffu, ps0, o);
            pd0 += __shfl_xor_sync(0xffffffffu, pd0, o);
            ps1 += __shfl_xor_sync(0xffffffffu, ps1, o);
            pd1 += __shfl_xor_sync(0xffffffffu, pd1, o);
        }
        if ((lane & 3) == 0) {
            if (r < M) { atomicAdd(&g_as[r], ps0); atomicAdd(&g_ad[r], pd0); }
            if (r + 8 < M) { atomicAdd(&g_as[r + 8], ps1); atomicAdd(&g_ad[r + 8], pd1); }
        }
    }
}

// ---------------- fused passAB: warp per dst; e + exp + segment sum ----------
__global__ void passAB_kernel(int n) {
    int w = (int)((blockIdx.x * (size_t)blockDim.x + threadIdx.x) >> 5);
    int lane = threadIdx.x & 31;
    if (w >= n) return;
    int off = g_off[w], deg = g_deg[w];
    float ad = __ldg(&g_ad[w]);
    float s = 0.f;
    for (int i = lane; i < deg; i += 32) {
        int src = __ldg(&g_csr_src[off + i]);
        float e = __ldg(&g_as[src]) + ad;
        e = (e > 0.f) ? e : NEG_SLOPE * e;
        float ex = __expf(e);
        g_e_csr[off + i] = ex;
        s += ex;
    }
    #pragma unroll
    for (int o = 16; o; o >>= 1) s += __shfl_xor_sync(0xffffffffu, s, o);
    if (lane == 0) g_s[w] = __frcp_rn(s);
}

// ---------------- passC layer 1: aggregate + bias + relu -> bf16 hi/lo -------
__global__ __launch_bounds__(896)
void passC_bf16_kernel(int n, const float* __restrict__ bias) {
    int t = blockIdx.x * 896 + threadIdx.x;
    int d = t / 56;
    int c = t % 56;
    if (d >= n) return;
    size_t base = (size_t)d * KP1 + c * 4;
    if (c >= 50) {
        *(uint2*)(g_ahi + base) = make_uint2(0, 0);
        *(uint2*)(g_alo + base) = make_uint2(0, 0);
        return;
    }
    float rs = __ldg(&g_s[d]);
    int off = g_off[d], deg = g_deg[d];
    float4 acc = __ldg((const float4*)bias + c);
    const float4* h4 = (const float4*)g_h;
    for (int j = 0; j < deg; j++) {
        int pos = off + j;
        float a = __ldg(&g_e_csr[pos]) * rs;
        int src = __ldg(&g_csr_src[pos]);
        float4 v = __ldg(h4 + (size_t)src * (OUT_C / 4) + c);
        acc.x = fmaf(a, v.x, acc.x);
        acc.y = fmaf(a, v.y, acc.y);
        acc.z = fmaf(a, v.z, acc.z);
        acc.w = fmaf(a, v.w, acc.w);
    }
    acc.x = fmaxf(acc.x, 0.f); acc.y = fmaxf(acc.y, 0.f);
    acc.z = fmaxf(acc.z, 0.f); acc.w = fmaxf(acc.w, 0.f);
    uint2 uh, ul;
    split4(acc, uh, ul);
    *(uint2*)(g_ahi + base) = uh;
    *(uint2*)(g_alo + base) = ul;
}

// ---------------- passC layer 2: aggregate + bias + relu -> fp32 out ---------
__global__ __launch_bounds__(800)
void passC_f32_kernel(int n, float* __restrict__ out,
                      const float* __restrict__ bias) {
    int t = blockIdx.x * 800 + threadIdx.x;
    int d = t / 50;
    int c = t % 50;
    if (d >= n) return;
    float rs = __ldg(&g_s[d]);
    int off = g_off[d], deg = g_deg[d];
    float4 acc = __ldg((const float4*)bias + c);
    const float4* h4 = (const float4*)g_h;
    for (int j = 0; j < deg; j++) {
        int pos = off + j;
        float a = __ldg(&g_e_csr[pos]) * rs;
        int src = __ldg(&g_csr_src[pos]);
        float4 v = __ldg(h4 + (size_t)src * (OUT_C / 4) + c);
        acc.x = fmaf(a, v.x, acc.x);
        acc.y = fmaf(a, v.y, acc.y);
        acc.z = fmaf(a, v.z, acc.z);
        acc.w = fmaf(a, v.w, acc.w);
    }
    acc.x = fmaxf(acc.x, 0.f); acc.y = fmaxf(acc.y, 0.f);
    acc.z = fmaxf(acc.z, 0.f); acc.w = fmaxf(acc.w, 0.f);
    ((float4*)out)[(size_t)d * (OUT_C / 4) + c] = acc;
}

// ---------------- launch -----------------------------------------------------
extern "C" void kernel_launch(void* const* d_in, const int* in_sizes, int n_in,
                              void* d_out, int out_size) {
    const float* x      = (const float*)d_in[0];
    const float* W0     = (const float*)d_in[1];
    const float* a_src0 = (const float*)d_in[2];
    const float* a_dst0 = (const float*)d_in[3];
    const float* b0     = (const float*)d_in[4];
    const float* W1     = (const float*)d_in[5];
    const float* a_src1 = (const float*)d_in[6];
    const float* a_dst1 = (const float*)d_in[7];
    const float* b1     = (const float*)d_in[8];
    const void*  ei     = d_in[9];

    int n    = in_sizes[0] / IN_C;   // 100000
    int E    = in_sizes[9] / 2;      // 1600000
    int Etot = E + n;

    cudaFuncSetAttribute(gemm_tc_kernel<true>,
                         cudaFuncAttributeMaxDynamicSharedMemorySize, GEMM_SMEM);
    cudaFuncSetAttribute(gemm_tc_kernel<false>,
                         cudaFuncAttributeMaxDynamicSharedMemorySize, GEMM_SMEM);

    dim3 gemm_grid((n + 127) / 128, 2);
    int node_blocks  = (n + 255) / 256;
    int edge_blocks  = (Etot + 511) / 512;
    int scan_blocks  = (n + 1023) / 1024;
    int warp_blocks  = (int)(((long long)n * 32 + 255) / 256);
    int aggC1_blocks = (int)(((long long)n * 56 + 895) / 896);
    int aggC2_blocks = (int)(((long long)n * 50 + 799) / 800);

    // ----- layer 1 front (gemm is 4th launch -> ncu capture) -----
    zero_asad_kernel<<<node_blocks, 256>>>(n);
    probe_kernel<<<1, 32>>>((const int*)ei);
    split_w_kernel<<<(NPAD * KP0 + 255) / 256, 256>>>(W0, IN_C, KP0);
    gemm_tc_kernel<true><<<gemm_grid, 256, GEMM_SMEM>>>(
        n, IN_C, IN_C, KP0, KP0 / 32, x, a_src0, a_dst0);

    // ----- CSR build -----
    zero_deg_kernel<<<node_blocks, 256>>>(n);
    hist_kernel<<<edge_blocks, 512>>>(ei, E, Etot);
    scan1_kernel<<<scan_blocks, 1024>>>(n);
    scan2_kernel<<<1, 128>>>(scan_blocks);
    scan3_kernel<<<node_blocks, 256>>>(n);
    fill_kernel<<<edge_blocks, 512>>>(ei, E, Etot);

    // ----- layer 1 back -----
    passAB_kernel<<<warp_blocks, 256>>>(n);
    passC_bf16_kernel<<<aggC1_blocks, 896>>>(n, b0);

    // ----- layer 2 -----
    zero_asad_kernel<<<node_blocks, 256>>>(n);
    split_w_kernel<<<(NPAD * KP1 + 255) / 256, 256>>>(W1, OUT_C, KP1);
    gemm_tc_kernel<false><<<gemm_grid, 256, GEMM_SMEM>>>(
        n, KP1, OUT_C, KP1, KP1 / 32, nullptr, a_src1, a_dst1);
    passAB_kernel<<<warp_blocks, 256>>>(n);
    passC_f32_kernel<<<aggC2_blocks, 800>>>(n, (float*)d_out, b1);
}

// round 14
// speedup vs baseline: 6.5839x; 1.2147x over previous
#include <cuda_runtime.h>
#include <cuda_bf16.h>
#include <cstdint>

#define N_NODES_MAX 100000
#define IN_C 300
#define OUT_C 200
#define E_MAX 1600000
#define ETOT_MAX (E_MAX + N_NODES_MAX)
#define NEG_SLOPE 0.2f

#define KP0 320
#define KP1 224
#define NPAD 256          // padded N for weight tiles (2 x BN=128)
#define SKP 40            // smem k pitch (halves)
#define TS (128 * SKP)    // halves per tile array
#define GEMM_SMEM (2 * 4 * TS * 2)  // 2 stages * 4 arrays * TS halves * 2B

// ---------------- scratch ----------------
__device__ float g_h[(size_t)N_NODES_MAX * OUT_C];
__device__ float g_as[N_NODES_MAX];
__device__ float g_ad[N_NODES_MAX];
__device__ float g_s[N_NODES_MAX];
__device__ int   g_idx64;
// CSR
__device__ int   g_deg[N_NODES_MAX];
__device__ int   g_off[N_NODES_MAX + 1];
__device__ int   g_cur[N_NODES_MAX];
__device__ int   g_bsum[256];
__device__ int   g_boff[257];
__device__ int   g_csr_src[ETOT_MAX];
__device__ int2  g_pair[ETOT_MAX];    // {src, float_bits(exp_e)} for passC
// bf16 split buffers (layer-2 A written by passC; weights per layer)
__device__ __nv_bfloat16 g_ahi[(size_t)N_NODES_MAX * KP1];
__device__ __nv_bfloat16 g_alo[(size_t)N_NODES_MAX * KP1];
__device__ __nv_bfloat16 g_whi[(size_t)NPAD * KP0];
__device__ __nv_bfloat16 g_wlo[(size_t)NPAD * KP0];

// ---------------- helpers ----------------
__device__ __forceinline__ int edge_at(const void* ei, int is64, long long pos) {
    if (is64) return (int)((const long long*)ei)[pos];
    return ((const int*)ei)[pos];
}

__device__ __forceinline__ uint32_t smem_u32(const void* p) {
    return (uint32_t)__cvta_generic_to_shared(p);
}

__device__ __forceinline__ void cp16(uint32_t dst, const void* src, bool pred) {
    int sz = pred ? 16 : 0;
    asm volatile("cp.async.cg.shared.global [%0], [%1], 16, %2;"
                 :: "r"(dst), "l"(src), "r"(sz));
}

#define CP_COMMIT() asm volatile("cp.async.commit_group;")
#define CP_WAIT(N)  asm volatile("cp.async.wait_group %0;" :: "n"(N))

#define LDSM_X4(r0, r1, r2, r3, addr)                                        \
    asm volatile("ldmatrix.sync.aligned.m8n8.x4.shared.b16 {%0,%1,%2,%3}, [%4];" \
                 : "=r"(r0), "=r"(r1), "=r"(r2), "=r"(r3) : "r"(addr))

#define MMA_BF16(d, a, b)                                                    \
    asm volatile("mma.sync.aligned.m16n8k16.row.col.f32.bf16.bf16.f32 "      \
                 "{%0,%1,%2,%3},{%4,%5,%6,%7},{%8,%9},{%0,%1,%2,%3};"        \
                 : "+f"(d[0]), "+f"(d[1]), "+f"(d[2]), "+f"(d[3])            \
                 : "r"(a[0]), "r"(a[1]), "r"(a[2]), "r"(a[3]),               \
                   "r"(b[0]), "r"(b[1]))

__device__ __forceinline__ void bf16_split(float v, __nv_bfloat16& hi, __nv_bfloat16& lo) {
    hi = __float2bfloat16(v);
    lo = __float2bfloat16(v - __bfloat162float(hi));
}

// split a float4 into packed hi (uint2) and lo (uint2) bf16x4
__device__ __forceinline__ void split4(float4 v, uint2& uh, uint2& ul) {
    __nv_bfloat162 h01 = __floats2bfloat162_rn(v.x, v.y);
    __nv_bfloat162 h23 = __floats2bfloat162_rn(v.z, v.w);
    float2 f01 = __bfloat1622float2(h01);
    float2 f23 = __bfloat1622float2(h23);
    __nv_bfloat162 l01 = __floats2bfloat162_rn(v.x - f01.x, v.y - f01.y);
    __nv_bfloat162 l23 = __floats2bfloat162_rn(v.z - f23.x, v.w - f23.y);
    uh.x = *(uint32_t*)&h01; uh.y = *(uint32_t*)&h23;
    ul.x = *(uint32_t*)&l01; ul.y = *(uint32_t*)&l23;
}

__global__ void probe_kernel(const int* ei) {
    if (threadIdx.x == 0 && blockIdx.x == 0) {
        int is64 = 1;
        #pragma unroll
        for (int i = 1; i < 32; i += 2)
            if (ei[i] != 0) { is64 = 0; break; }
        g_idx64 = is64;
    }
}

__global__ void zero_asad_kernel(int n) {
    int i = blockIdx.x * blockDim.x + threadIdx.x;
    if (i < n) { g_as[i] = 0.f; g_ad[i] = 0.f; }
}

// ---------------- CSR build --------------------------------------------------
__global__ void zero_deg_kernel(int n) {
    int i = blockIdx.x * blockDim.x + threadIdx.x;
    if (i < n) g_deg[i] = 0;
}

__global__ void hist_kernel(const void* __restrict__ ei, int E, int Etot) {
    int i = blockIdx.x * blockDim.x + threadIdx.x;
    if (i >= Etot) return;
    int is64 = g_idx64;
    int dst = (i < E) ? edge_at(ei, is64, (long long)E + i) : (i - E);
    atomicAdd(&g_deg[dst], 1);
}

__global__ __launch_bounds__(1024) void scan1_kernel(int n) {
    __shared__ int sh[1024];
    int t = threadIdx.x;
    int i = blockIdx.x * 1024 + t;
    int v = (i < n) ? g_deg[i] : 0;
    sh[t] = v;
    __syncthreads();
    #pragma unroll
    for (int o = 1; o < 1024; o <<= 1) {
        int u = (t >= o) ? sh[t - o] : 0;
        __syncthreads();
        sh[t] += u;
        __syncthreads();
    }
    if (i < n) g_off[i] = sh[t] - v;
    if (t == 1023) g_bsum[blockIdx.x] = sh[1023];
}

__global__ __launch_bounds__(128) void scan2_kernel(int nb) {
    __shared__ int sh[128];
    int t = threadIdx.x;
    int v = (t < nb) ? g_bsum[t] : 0;
    sh[t] = v;
    __syncthreads();
    #pragma unroll
    for (int o = 1; o < 128; o <<= 1) {
        int u = (t >= o) ? sh[t - o] : 0;
        __syncthreads();
        sh[t] += u;
        __syncthreads();
    }
    g_boff[t] = sh[t] - v;
    if (t == 127) g_boff[128] = sh[127];
}

__global__ void scan3_kernel(int n) {
    int i = blockIdx.x * blockDim.x + threadIdx.x;
    if (i < n) {
        int o = g_off[i] + g_boff[i >> 10];
        g_off[i] = o;
        g_cur[i] = o;
    }
    if (i == 0) g_off[n] = g_boff[128];
}

__global__ void fill_kernel(const void* __restrict__ ei, int E, int Etot) {
    int i = blockIdx.x * blockDim.x + threadIdx.x;
    if (i >= Etot) return;
    int is64 = g_idx64;
    int src, dst;
    if (i < E) {
        src = edge_at(ei, is64, i);
        dst = edge_at(ei, is64, (long long)E + i);
    } else {
        src = dst = i - E;
    }
    int pos = atomicAdd(&g_cur[dst], 1);
    g_csr_src[pos] = src;
}

// ---------------- split W -----------------------------------------------------
__global__ void split_w_kernel(const float* __restrict__ W, int K, int KP) {
    int idx = blockIdx.x * blockDim.x + threadIdx.x;
    if (idx >= NPAD * KP) return;
    int k = idx % KP;
    int n = idx / KP;
    float v = (k < K && n < OUT_C) ? W[(size_t)k * OUT_C + n] : 0.f;
    __nv_bfloat16 hi, lo;
    bf16_split(v, hi, lo);
    g_whi[idx] = hi;
    g_wlo[idx] = lo;
}

// ---------------- tensor-core GEMM + fused alpha epilogue --------------------
// BM=128, BN=128, 8 warps (2m x 4n), warp tile 64x32. 2 CTAs/SM enforced.
// AFP32: A loaded as fp32 (layer-1 x), split to bf16 hi/lo in-register.
// !AFP32: A loaded from g_ahi/g_alo via cp.async (layer 2).
template<bool AFP32>
__global__ __launch_bounds__(256, 2)
void gemm_tc_kernel(int M, int ldaA, int Kin, int ldaB, int kblocks,
                    const float* __restrict__ Afp,
                    const float* __restrict__ a_src,
                    const float* __restrict__ a_dst) {
    extern __shared__ __nv_bfloat16 smem[];

    int tid = threadIdx.x;
    int lane = tid & 31, warp = tid >> 5;
    int wm = warp & 1, wn = warp >> 1;
    int bm = blockIdx.x * 128;
    int n0 = blockIdx.y * 128;

    float acc[4][4][4];
    #pragma unroll
    for (int i = 0; i < 4; i++)
        #pragma unroll
        for (int j = 0; j < 4; j++)
            #pragma unroll
            for (int q = 0; q < 4; q++) acc[i][j][q] = 0.f;

    int a_r = lane & 15, a_c = (lane >> 4) << 3;
    int b_r = (lane & 7) + ((lane >> 4) << 3);
    int b_c = ((lane >> 3) & 1) << 3;

    auto load_stage = [&](int kb, int s) {
        __nv_bfloat16* sAh = smem + s * 4 * TS;
        __nv_bfloat16* sAl = sAh + TS;
        __nv_bfloat16* sBh = sAl + TS;
        __nv_bfloat16* sBl = sBh + TS;
        if (AFP32) {
            // A: 128 rows x 32 floats = 1024 float4 loads over 256 threads
            #pragma unroll
            for (int i = 0; i < 4; i++) {
                int idx = tid + i * 256;
                int row = idx >> 3, qf = idx & 7;
                int gk = kb * 32 + qf * 4;
                float4 f = make_float4(0.f, 0.f, 0.f, 0.f);
                if ((bm + row) < M && (gk + 4) <= Kin)
                    f = *(const float4*)(Afp + (size_t)(bm + row) * ldaA + gk);
                uint2 uh, ul;
                split4(f, uh, ul);
                *(uint2*)(sAh + row * SKP + qf * 4) = uh;
                *(uint2*)(sAl + row * SKP + qf * 4) = ul;
            }
        } else {
            extern __device__ __nv_bfloat16 g_ahi[], g_alo[];
            #pragma unroll
            for (int i = 0; i < 2; i++) {
                int idx = tid + i * 256;
                int row = idx >> 2, q = idx & 3;
                bool vA = (bm + row) < M;
                int rA = vA ? (bm + row) : 0;
                size_t offA = (size_t)rA * ldaA + kb * 32 + q * 8;
                cp16(smem_u32(sAh + row * SKP + q * 8), g_ahi + offA, vA);
                cp16(smem_u32(sAl + row * SKP + q * 8), g_alo + offA, vA);
            }
        }
        #pragma unroll
        for (int i = 0; i < 2; i++) {
            int idx = tid + i * 256;
            int row = idx >> 2, q = idx & 3;
            size_t offB = (size_t)(n0 + row) * ldaB + kb * 32 + q * 8;
            cp16(smem_u32(sBh + row * SKP + q * 8), g_whi + offB, true);
            cp16(smem_u32(sBl + row * SKP + q * 8), g_wlo + offB, true);
        }
        CP_COMMIT();
    };

    load_stage(0, 0);

    for (int kb = 0; kb < kblocks; kb++) {
        if (kb + 1 < kblocks) {
            load_stage(kb + 1, (kb + 1) & 1);
            CP_WAIT(1);
        } else {
            CP_WAIT(0);
        }
        __syncthreads();

        int s = kb & 1;
        __nv_bfloat16* sAh = smem + s * 4 * TS;
        __nv_bfloat16* sAl = sAh + TS;
        __nv_bfloat16* sBh = sAl + TS;
        __nv_bfloat16* sBl = sBh + TS;

        #pragma unroll
        for (int ks = 0; ks < 2; ks++) {
            int kh = ks * 16;
            uint32_t ah[4][4], al[4][4], bh[4][2], bl[4][2];
            #pragma unroll
            for (int mi = 0; mi < 4; mi++) {
                int row = wm * 64 + mi * 16 + a_r;
                uint32_t ad = smem_u32(sAh + row * SKP + kh + a_c);
                LDSM_X4(ah[mi][0], ah[mi][1], ah[mi][2], ah[mi][3], ad);
                ad = smem_u32(sAl + row * SKP + kh + a_c);
                LDSM_X4(al[mi][0], al[mi][1], al[mi][2], al[mi][3], ad);
            }
            #pragma unroll
            for (int nj = 0; nj < 2; nj++) {
                int row = wn * 32 + nj * 16 + b_r;
                uint32_t ad = smem_u32(sBh + row * SKP + kh + b_c);
                LDSM_X4(bh[2 * nj][0], bh[2 * nj][1], bh[2 * nj + 1][0], bh[2 * nj + 1][1], ad);
                ad = smem_u32(sBl + row * SKP + kh + b_c);
                LDSM_X4(bl[2 * nj][0], bl[2 * nj][1], bl[2 * nj + 1][0], bl[2 * nj + 1][1], ad);
            }
            #pragma unroll
            for (int mi = 0; mi < 4; mi++)
                #pragma unroll
                for (int ni = 0; ni < 4; ni++) {
                    MMA_BF16(acc[mi][ni], ah[mi], bh[ni]);
                    MMA_BF16(acc[mi][ni], ah[mi], bl[ni]);
                    MMA_BF16(acc[mi][ni], al[mi], bh[ni]);
                }
        }
        __syncthreads();
    }

    float vs0[4], vs1[4], vd0[4], vd1[4];
    #pragma unroll
    for (int ni = 0; ni < 4; ni++) {
        int c = n0 + wn * 32 + ni * 8 + ((lane & 3) << 1);
        vs0[ni] = (c < OUT_C) ? __ldg(a_src + c) : 0.f;
        vs1[ni] = (c + 1 < OUT_C) ? __ldg(a_src + c + 1) : 0.f;
        vd0[ni] = (c < OUT_C) ? __ldg(a_dst + c) : 0.f;
        vd1[ni] = (c + 1 < OUT_C) ? __ldg(a_dst + c + 1) : 0.f;
    }

    #pragma unroll
    for (int mi = 0; mi < 4; mi++) {
        int r = bm + wm * 64 + mi * 16 + (lane >> 2);
        #pragma unroll
        for (int ni = 0; ni < 4; ni++) {
            int c = n0 + wn * 32 + ni * 8 + ((lane & 3) << 1);
            if (c >= OUT_C) continue;
            if (r < M)
                *(float2*)(g_h + (size_t)r * OUT_C + c) =
                    make_float2(acc[mi][ni][0], acc[mi][ni][1]);
            if (r + 8 < M)
                *(float2*)(g_h + (size_t)(r + 8) * OUT_C + c) =
                    make_float2(acc[mi][ni][2], acc[mi][ni][3]);
        }
        float ps0 = 0.f, pd0 = 0.f, ps1 = 0.f, pd1 = 0.f;
        #pragma unroll
        for (int ni = 0; ni < 4; ni++) {
            ps0 += acc[mi][ni][0] * vs0[ni] + acc[mi][ni][1] * vs1[ni];
            pd0 += acc[mi][ni][0] * vd0[ni] + acc[mi][ni][1] * vd1[ni];
            ps1 += acc[mi][ni][2] * vs0[ni] + acc[mi][ni][3] * vs1[ni];
            pd1 += acc[mi][ni][2] * vd0[ni] + acc[mi][ni][3] * vd1[ni];
        }
        #pragma unroll
        for (int o = 1; o <= 2; o <<= 1) {
            ps0 += __shfl_xor_sync(0xffffffffu, ps0, o);
            pd0 += __shfl_xor_sync(0xffffffffu, pd0, o);
            ps1 += __shfl_xor_sync(0xffffffffu, ps1, o);
            pd1 += __shfl_xor_sync(0xffffffffu, pd1, o);
        }
        if ((lane & 3) == 0) {
            if (r < M) { atomicAdd(&g_as[r], ps0); atomicAdd(&g_ad[r], pd0); }
            if (r + 8 < M) { atomicAdd(&g_as[r + 8], ps1); atomicAdd(&g_ad[r + 8], pd1); }
        }
    }
}

// ---------------- fused passAB: warp per dst; e + exp + segment sum ----------
// Writes packed {src, exp_e} records for passC.
__global__ void passAB_kernel(int n) {
    int w = (int)((blockIdx.x * (size_t)blockDim.x + threadIdx.x) >> 5);
    int lane = threadIdx.x & 31;
    if (w >= n) return;
    int off = g_off[w], deg = g_deg[w];
    float ad = __ldg(&g_ad[w]);
    float s = 0.f;
    for (int i = lane; i < deg; i += 32) {
        int src = __ldg(&g_csr_src[off + i]);
        float e = __ldg(&g_as[src]) + ad;
        e = (e > 0.f) ? e : NEG_SLOPE * e;
        float ex = __expf(e);
        g_pair[off + i] = make_int2(src, __float_as_int(ex));
        s += ex;
    }
    #pragma unroll
    for (int o = 16; o; o >>= 1) s += __shfl_xor_sync(0xffffffffu, s, o);
    if (lane == 0) g_s[w] = __frcp_rn(s);
}

// ---------------- passC layer 1: aggregate + bias + relu -> bf16 hi/lo -------
__global__ __launch_bounds__(896)
void passC_bf16_kernel(int n, const float* __restrict__ bias) {
    int t = blockIdx.x * 896 + threadIdx.x;
    int d = t / 56;
    int c = t % 56;
    if (d >= n) return;
    size_t base = (size_t)d * KP1 + c * 4;
    if (c >= 50) {
        *(uint2*)(g_ahi + base) = make_uint2(0, 0);
        *(uint2*)(g_alo + base) = make_uint2(0, 0);
        return;
    }
    float rs = __ldg(&g_s[d]);
    int off = g_off[d], deg = g_deg[d];
    float4 acc = __ldg((const float4*)bias + c);
    const float4* h4 = (const float4*)g_h;
    for (int j = 0; j < deg; j++) {
        int2 p = __ldg(&g_pair[off + j]);
        float a = __int_as_float(p.y) * rs;
        float4 v = __ldg(h4 + (size_t)p.x * (OUT_C / 4) + c);
        acc.x = fmaf(a, v.x, acc.x);
        acc.y = fmaf(a, v.y, acc.y);
        acc.z = fmaf(a, v.z, acc.z);
        acc.w = fmaf(a, v.w, acc.w);
    }
    acc.x = fmaxf(acc.x, 0.f); acc.y = fmaxf(acc.y, 0.f);
    acc.z = fmaxf(acc.z, 0.f); acc.w = fmaxf(acc.w, 0.f);
    uint2 uh, ul;
    split4(acc, uh, ul);
    *(uint2*)(g_ahi + base) = uh;
    *(uint2*)(g_alo + base) = ul;
}

// ---------------- passC layer 2: aggregate + bias + relu -> fp32 out ---------
__global__ __launch_bounds__(800)
void passC_f32_kernel(int n, float* __restrict__ out,
                      const float* __restrict__ bias) {
    int t = blockIdx.x * 800 + threadIdx.x;
    int d = t / 50;
    int c = t % 50;
    if (d >= n) return;
    float rs = __ldg(&g_s[d]);
    int off = g_off[d], deg = g_deg[d];
    float4 acc = __ldg((const float4*)bias + c);
    const float4* h4 = (const float4*)g_h;
    for (int j = 0; j < deg; j++) {
        int2 p = __ldg(&g_pair[off + j]);
        float a = __int_as_float(p.y) * rs;
        float4 v = __ldg(h4 + (size_t)p.x * (OUT_C / 4) + c);
        acc.x = fmaf(a, v.x, acc.x);
        acc.y = fmaf(a, v.y, acc.y);
        acc.z = fmaf(a, v.z, acc.z);
        acc.w = fmaf(a, v.w, acc.w);
    }
    acc.x = fmaxf(acc.x, 0.f); acc.y = fmaxf(acc.y, 0.f);
    acc.z = fmaxf(acc.z, 0.f); acc.w = fmaxf(acc.w, 0.f);
    ((float4*)out)[(size_t)d * (OUT_C / 4) + c] = acc;
}

// ---------------- launch -----------------------------------------------------
extern "C" void kernel_launch(void* const* d_in, const int* in_sizes, int n_in,
                              void* d_out, int out_size) {
    const float* x      = (const float*)d_in[0];
    const float* W0     = (const float*)d_in[1];
    const float* a_src0 = (const float*)d_in[2];
    const float* a_dst0 = (const float*)d_in[3];
    const float* b0     = (const float*)d_in[4];
    const float* W1     = (const float*)d_in[5];
    const float* a_src1 = (const float*)d_in[6];
    const float* a_dst1 = (const float*)d_in[7];
    const float* b1     = (const float*)d_in[8];
    const void*  ei     = d_in[9];

    int n    = in_sizes[0] / IN_C;   // 100000
    int E    = in_sizes[9] / 2;      // 1600000
    int Etot = E + n;

    cudaFuncSetAttribute(gemm_tc_kernel<true>,
                         cudaFuncAttributeMaxDynamicSharedMemorySize, GEMM_SMEM);
    cudaFuncSetAttribute(gemm_tc_kernel<false>,
                         cudaFuncAttributeMaxDynamicSharedMemorySize, GEMM_SMEM);

    dim3 gemm_grid((n + 127) / 128, 2);
    int node_blocks  = (n + 255) / 256;
    int edge_blocks  = (Etot + 511) / 512;
    int scan_blocks  = (n + 1023) / 1024;
    int warp_blocks  = (int)(((long long)n * 32 + 255) / 256);
    int aggC1_blocks = (int)(((long long)n * 56 + 895) / 896);
    int aggC2_blocks = (int)(((long long)n * 50 + 799) / 800);

    // ----- layer 1 front (gemm is 4th launch -> ncu capture) -----
    zero_asad_kernel<<<node_blocks, 256>>>(n);
    probe_kernel<<<1, 32>>>((const int*)ei);
    split_w_kernel<<<(NPAD * KP0 + 255) / 256, 256>>>(W0, IN_C, KP0);
    gemm_tc_kernel<true><<<gemm_grid, 256, GEMM_SMEM>>>(
        n, IN_C, IN_C, KP0, KP0 / 32, x, a_src0, a_dst0);

    // ----- CSR build -----
    zero_deg_kernel<<<node_blocks, 256>>>(n);
    hist_kernel<<<edge_blocks, 512>>>(ei, E, Etot);
    scan1_kernel<<<scan_blocks, 1024>>>(n);
    scan2_kernel<<<1, 128>>>(scan_blocks);
    scan3_kernel<<<node_blocks, 256>>>(n);
    fill_kernel<<<edge_blocks, 512>>>(ei, E, Etot);

    // ----- layer 1 back -----
    passAB_kernel<<<warp_blocks, 256>>>(n);
    passC_bf16_kernel<<<aggC1_blocks, 896>>>(n, b0);

    // ----- layer 2 -----
    zero_asad_kernel<<<node_blocks, 256>>>(n);
    split_w_kernel<<<(NPAD * KP1 + 255) / 256, 256>>>(W1, OUT_C, KP1);
    gemm_tc_kernel<false><<<gemm_grid, 256, GEMM_SMEM>>>(
        n, KP1, OUT_C, KP1, KP1 / 32, nullptr, a_src1, a_dst1);
    passAB_kernel<<<warp_blocks, 256>>>(n);
    passC_f32_kernel<<<aggC2_blocks, 800>>>(n, (float*)d_out, b1);
}

// round 15
// speedup vs baseline: 6.7043x; 1.0183x over previous
#include <cuda_runtime.h>
#include <cuda_bf16.h>
#include <cstdint>

#define N_NODES_MAX 100000
#define IN_C 300
#define OUT_C 200
#define E_MAX 1600000
#define ETOT_MAX (E_MAX + N_NODES_MAX)
#define NEG_SLOPE 0.2f

#define KP0 320
#define KP1 224
#define NPAD 256          // padded N for weight tiles (2 x BN=128)
#define SKP 40            // smem k pitch (halves)
#define TS (128 * SKP)    // halves per tile array
#define GEMM_SMEM (2 * 4 * TS * 2)  // 2 stages * 4 arrays * TS halves * 2B

// ---------------- scratch ----------------
__device__ float g_h[(size_t)N_NODES_MAX * OUT_C];
__device__ float g_as[N_NODES_MAX];
__device__ float g_ad[N_NODES_MAX];
__device__ float g_s[N_NODES_MAX];
__device__ int   g_idx64;
// CSR
__device__ int   g_deg[N_NODES_MAX];
__device__ int   g_off[N_NODES_MAX + 1];
__device__ int   g_cur[N_NODES_MAX];
__device__ int   g_bsum[256];
__device__ int   g_boff[257];
__device__ int   g_csr_src[ETOT_MAX];
__device__ int2  g_pair[ETOT_MAX];    // {src, float_bits(exp_e)} for passC
// bf16 split buffers (layer-2 A written by passC; weights per layer)
__device__ __nv_bfloat16 g_ahi[(size_t)N_NODES_MAX * KP1];
__device__ __nv_bfloat16 g_alo[(size_t)N_NODES_MAX * KP1];
__device__ __nv_bfloat16 g_whi[(size_t)NPAD * KP0];
__device__ __nv_bfloat16 g_wlo[(size_t)NPAD * KP0];

// ---------------- helpers ----------------
__device__ __forceinline__ int edge_at(const void* ei, int is64, long long pos) {
    if (is64) return (int)((const long long*)ei)[pos];
    return ((const int*)ei)[pos];
}

__device__ __forceinline__ uint32_t smem_u32(const void* p) {
    return (uint32_t)__cvta_generic_to_shared(p);
}

__device__ __forceinline__ void cp16(uint32_t dst, const void* src, bool pred) {
    int sz = pred ? 16 : 0;
    asm volatile("cp.async.cg.shared.global [%0], [%1], 16, %2;"
                 :: "r"(dst), "l"(src), "r"(sz));
}

#define CP_COMMIT() asm volatile("cp.async.commit_group;")
#define CP_WAIT(N)  asm volatile("cp.async.wait_group %0;" :: "n"(N))

#define LDSM_X4(r0, r1, r2, r3, addr)                                        \
    asm volatile("ldmatrix.sync.aligned.m8n8.x4.shared.b16 {%0,%1,%2,%3}, [%4];" \
                 : "=r"(r0), "=r"(r1), "=r"(r2), "=r"(r3) : "r"(addr))

#define MMA_BF16(d, a, b)                                                    \
    asm volatile("mma.sync.aligned.m16n8k16.row.col.f32.bf16.bf16.f32 "      \
                 "{%0,%1,%2,%3},{%4,%5,%6,%7},{%8,%9},{%0,%1,%2,%3};"        \
                 : "+f"(d[0]), "+f"(d[1]), "+f"(d[2]), "+f"(d[3])            \
                 : "r"(a[0]), "r"(a[1]), "r"(a[2]), "r"(a[3]),               \
                   "r"(b[0]), "r"(b[1]))

__device__ __forceinline__ void bf16_split(float v, __nv_bfloat16& hi, __nv_bfloat16& lo) {
    hi = __float2bfloat16(v);
    lo = __float2bfloat16(v - __bfloat162float(hi));
}

// split a float4 into packed hi (uint2) and lo (uint2) bf16x4
__device__ __forceinline__ void split4(float4 v, uint2& uh, uint2& ul) {
    __nv_bfloat162 h01 = __floats2bfloat162_rn(v.x, v.y);
    __nv_bfloat162 h23 = __floats2bfloat162_rn(v.z, v.w);
    float2 f01 = __bfloat1622float2(h01);
    float2 f23 = __bfloat1622float2(h23);
    __nv_bfloat162 l01 = __floats2bfloat162_rn(v.x - f01.x, v.y - f01.y);
    __nv_bfloat162 l23 = __floats2bfloat162_rn(v.z - f23.x, v.w - f23.y);
    uh.x = *(uint32_t*)&h01; uh.y = *(uint32_t*)&h23;
    ul.x = *(uint32_t*)&l01; ul.y = *(uint32_t*)&l23;
}

__global__ void probe_kernel(const int* ei) {
    if (threadIdx.x == 0 && blockIdx.x == 0) {
        int is64 = 1;
        #pragma unroll
        for (int i = 1; i < 32; i += 2)
            if (ei[i] != 0) { is64 = 0; break; }
        g_idx64 = is64;
    }
}

__global__ void zero_asad_kernel(int n) {
    int i = blockIdx.x * blockDim.x + threadIdx.x;
    if (i < n) { g_as[i] = 0.f; g_ad[i] = 0.f; }
}

// ---------------- CSR build --------------------------------------------------
__global__ void zero_deg_kernel(int n) {
    int i = blockIdx.x * blockDim.x + threadIdx.x;
    if (i < n) g_deg[i] = 0;
}

__global__ void hist_kernel(const void* __restrict__ ei, int E, int Etot) {
    int i = blockIdx.x * blockDim.x + threadIdx.x;
    if (i >= Etot) return;
    int is64 = g_idx64;
    int dst = (i < E) ? edge_at(ei, is64, (long long)E + i) : (i - E);
    atomicAdd(&g_deg[dst], 1);
}

__global__ __launch_bounds__(1024) void scan1_kernel(int n) {
    __shared__ int sh[1024];
    int t = threadIdx.x;
    int i = blockIdx.x * 1024 + t;
    int v = (i < n) ? g_deg[i] : 0;
    sh[t] = v;
    __syncthreads();
    #pragma unroll
    for (int o = 1; o < 1024; o <<= 1) {
        int u = (t >= o) ? sh[t - o] : 0;
        __syncthreads();
        sh[t] += u;
        __syncthreads();
    }
    if (i < n) g_off[i] = sh[t] - v;
    if (t == 1023) g_bsum[blockIdx.x] = sh[1023];
}

__global__ __launch_bounds__(128) void scan2_kernel(int nb) {
    __shared__ int sh[128];
    int t = threadIdx.x;
    int v = (t < nb) ? g_bsum[t] : 0;
    sh[t] = v;
    __syncthreads();
    #pragma unroll
    for (int o = 1; o < 128; o <<= 1) {
        int u = (t >= o) ? sh[t - o] : 0;
        __syncthreads();
        sh[t] += u;
        __syncthreads();
    }
    g_boff[t] = sh[t] - v;
    if (t == 127) g_boff[128] = sh[127];
}

__global__ void scan3_kernel(int n) {
    int i = blockIdx.x * blockDim.x + threadIdx.x;
    if (i < n) {
        int o = g_off[i] + g_boff[i >> 10];
        g_off[i] = o;
        g_cur[i] = o;
    }
    if (i == 0) g_off[n] = g_boff[128];
}

__global__ void fill_kernel(const void* __restrict__ ei, int E, int Etot) {
    int i = blockIdx.x * blockDim.x + threadIdx.x;
    if (i >= Etot) return;
    int is64 = g_idx64;
    int src, dst;
    if (i < E) {
        src = edge_at(ei, is64, i);
        dst = edge_at(ei, is64, (long long)E + i);
    } else {
        src = dst = i - E;
    }
    int pos = atomicAdd(&g_cur[dst], 1);
    g_csr_src[pos] = src;
}

// ---------------- split W -----------------------------------------------------
__global__ void split_w_kernel(const float* __restrict__ W, int K, int KP) {
    int idx = blockIdx.x * blockDim.x + threadIdx.x;
    if (idx >= NPAD * KP) return;
    int k = idx % KP;
    int n = idx / KP;
    float v = (k < K && n < OUT_C) ? W[(size_t)k * OUT_C + n] : 0.f;
    __nv_bfloat16 hi, lo;
    bf16_split(v, hi, lo);
    g_whi[idx] = hi;
    g_wlo[idx] = lo;
}

// ---------------- tensor-core GEMM + fused alpha epilogue --------------------
// BM=128, BN=128, 8 warps (2m x 4n), warp tile 64x32. 2 CTAs/SM enforced.
// Grid: (2, m_tiles) — x = n-tile, y = m-tile, so both n-tiles of an m-tile
// are adjacent in launch order and the second one's A-reads hit L2.
// AFP32: A loaded as fp32 (layer-1 x), split to bf16 hi/lo in-register.
// !AFP32: A loaded from g_ahi/g_alo via cp.async (layer 2).
template<bool AFP32>
__global__ __launch_bounds__(256, 2)
void gemm_tc_kernel(int M, int ldaA, int Kin, int ldaB, int kblocks,
                    const float* __restrict__ Afp,
                    const float* __restrict__ a_src,
                    const float* __restrict__ a_dst) {
    extern __shared__ __nv_bfloat16 smem[];

    int tid = threadIdx.x;
    int lane = tid & 31, warp = tid >> 5;
    int wm = warp & 1, wn = warp >> 1;
    int bm = blockIdx.y * 128;          // m-tile (slow axis)
    int n0 = blockIdx.x * 128;          // n-tile (fast axis -> L2 A reuse)

    float acc[4][4][4];
    #pragma unroll
    for (int i = 0; i < 4; i++)
        #pragma unroll
        for (int j = 0; j < 4; j++)
            #pragma unroll
            for (int q = 0; q < 4; q++) acc[i][j][q] = 0.f;

    int a_r = lane & 15, a_c = (lane >> 4) << 3;
    int b_r = (lane & 7) + ((lane >> 4) << 3);
    int b_c = ((lane >> 3) & 1) << 3;

    auto load_stage = [&](int kb, int s) {
        __nv_bfloat16* sAh = smem + s * 4 * TS;
        __nv_bfloat16* sAl = sAh + TS;
        __nv_bfloat16* sBh = sAl + TS;
        __nv_bfloat16* sBl = sBh + TS;
        if (AFP32) {
            // A: 128 rows x 32 floats = 1024 float4 loads over 256 threads
            #pragma unroll
            for (int i = 0; i < 4; i++) {
                int idx = tid + i * 256;
                int row = idx >> 3, qf = idx & 7;
                int gk = kb * 32 + qf * 4;
                float4 f = make_float4(0.f, 0.f, 0.f, 0.f);
                if ((bm + row) < M && (gk + 4) <= Kin)
                    f = *(const float4*)(Afp + (size_t)(bm + row) * ldaA + gk);
                uint2 uh, ul;
                split4(f, uh, ul);
                *(uint2*)(sAh + row * SKP + qf * 4) = uh;
                *(uint2*)(sAl + row * SKP + qf * 4) = ul;
            }
        } else {
            extern __device__ __nv_bfloat16 g_ahi[], g_alo[];
            #pragma unroll
            for (int i = 0; i < 2; i++) {
                int idx = tid + i * 256;
                int row = idx >> 2, q = idx & 3;
                bool vA = (bm + row) < M;
                int rA = vA ? (bm + row) : 0;
                size_t offA = (size_t)rA * ldaA + kb * 32 + q * 8;
                cp16(smem_u32(sAh + row * SKP + q * 8), g_ahi + offA, vA);
                cp16(smem_u32(sAl + row * SKP + q * 8), g_alo + offA, vA);
            }
        }
        #pragma unroll
        for (int i = 0; i < 2; i++) {
            int idx = tid + i * 256;
            int row = idx >> 2, q = idx & 3;
            size_t offB = (size_t)(n0 + row) * ldaB + kb * 32 + q * 8;
            cp16(smem_u32(sBh + row * SKP + q * 8), g_whi + offB, true);
            cp16(smem_u32(sBl + row * SKP + q * 8), g_wlo + offB, true);
        }
        CP_COMMIT();
    };

    load_stage(0, 0);

    for (int kb = 0; kb < kblocks; kb++) {
        if (kb + 1 < kblocks) {
            load_stage(kb + 1, (kb + 1) & 1);
            CP_WAIT(1);
        } else {
            CP_WAIT(0);
        }
        __syncthreads();

        int s = kb & 1;
        __nv_bfloat16* sAh = smem + s * 4 * TS;
        __nv_bfloat16* sAl = sAh + TS;
        __nv_bfloat16* sBh = sAl + TS;
        __nv_bfloat16* sBl = sBh + TS;

        #pragma unroll
        for (int ks = 0; ks < 2; ks++) {
            int kh = ks * 16;
            uint32_t ah[4][4], al[4][4], bh[4][2], bl[4][2];
            #pragma unroll
            for (int mi = 0; mi < 4; mi++) {
                int row = wm * 64 + mi * 16 + a_r;
                uint32_t ad = smem_u32(sAh + row * SKP + kh + a_c);
                LDSM_X4(ah[mi][0], ah[mi][1], ah[mi][2], ah[mi][3], ad);
                ad = smem_u32(sAl + row * SKP + kh + a_c);
                LDSM_X4(al[mi][0], al[mi][1], al[mi][2], al[mi][3], ad);
            }
            #pragma unroll
            for (int nj = 0; nj < 2; nj++) {
                int row = wn * 32 + nj * 16 + b_r;
                uint32_t ad = smem_u32(sBh + row * SKP + kh + b_c);
                LDSM_X4(bh[2 * nj][0], bh[2 * nj][1], bh[2 * nj + 1][0], bh[2 * nj + 1][1], ad);
                ad = smem_u32(sBl + row * SKP + kh + b_c);
                LDSM_X4(bl[2 * nj][0], bl[2 * nj][1], bl[2 * nj + 1][0], bl[2 * nj + 1][1], ad);
            }
            #pragma unroll
            for (int mi = 0; mi < 4; mi++)
                #pragma unroll
                for (int ni = 0; ni < 4; ni++) {
                    MMA_BF16(acc[mi][ni], ah[mi], bh[ni]);
                    MMA_BF16(acc[mi][ni], ah[mi], bl[ni]);
                    MMA_BF16(acc[mi][ni], al[mi], bh[ni]);
                }
        }
        __syncthreads();
    }

    float vs0[4], vs1[4], vd0[4], vd1[4];
    #pragma unroll
    for (int ni = 0; ni < 4; ni++) {
        int c = n0 + wn * 32 + ni * 8 + ((lane & 3) << 1);
        vs0[ni] = (c < OUT_C) ? __ldg(a_src + c) : 0.f;
        vs1[ni] = (c + 1 < OUT_C) ? __ldg(a_src + c + 1) : 0.f;
        vd0[ni] = (c < OUT_C) ? __ldg(a_dst + c) : 0.f;
        vd1[ni] = (c + 1 < OUT_C) ? __ldg(a_dst + c + 1) : 0.f;
    }

    #pragma unroll
    for (int mi = 0; mi < 4; mi++) {
        int r = bm + wm * 64 + mi * 16 + (lane >> 2);
        #pragma unroll
        for (int ni = 0; ni < 4; ni++) {
            int c = n0 + wn * 32 + ni * 8 + ((lane & 3) << 1);
            if (c >= OUT_C) continue;
            if (r < M)
                *(float2*)(g_h + (size_t)r * OUT_C + c) =
                    make_float2(acc[mi][ni][0], acc[mi][ni][1]);
            if (r + 8 < M)
                *(float2*)(g_h + (size_t)(r + 8) * OUT_C + c) =
                    make_float2(acc[mi][ni][2], acc[mi][ni][3]);
        }
        float ps0 = 0.f, pd0 = 0.f, ps1 = 0.f, pd1 = 0.f;
        #pragma unroll
        for (int ni = 0; ni < 4; ni++) {
            ps0 += acc[mi][ni][0] * vs0[ni] + acc[mi][ni][1] * vs1[ni];
            pd0 += acc[mi][ni][0] * vd0[ni] + acc[mi][ni][1] * vd1[ni];
            ps1 += acc[mi][ni][2] * vs0[ni] + acc[mi][ni][3] * vs1[ni];
            pd1 += acc[mi][ni][2] * vd0[ni] + acc[mi][ni][3] * vd1[ni];
        }
        #pragma unroll
        for (int o = 1; o <= 2; o <<= 1) {
            ps0 += __shfl_xor_sync(0xffffffffu, ps0, o);
            pd0 += __shfl_xor_sync(0xffffffffu, pd0, o);
            ps1 += __shfl_xor_sync(0xffffffffu, ps1, o);
            pd1 += __shfl_xor_sync(0xffffffffu, pd1, o);
        }
        if ((lane & 3) == 0) {
            if (r < M) { atomicAdd(&g_as[r], ps0); atomicAdd(&g_ad[r], pd0); }
            if (r + 8 < M) { atomicAdd(&g_as[r + 8], ps1); atomicAdd(&g_ad[r + 8], pd1); }
        }
    }
}

// ---------------- fused passAB: warp per dst; e + exp + segment sum ----------
// Writes packed {src, exp_e} records for passC.
__global__ void passAB_kernel(int n) {
    int w = (int)((blockIdx.x * (size_t)blockDim.x + threadIdx.x) >> 5);
    int lane = threadIdx.x & 31;
    if (w >= n) return;
    int off = g_off[w], deg = g_deg[w];
    float ad = __ldg(&g_ad[w]);
    float s = 0.f;
    for (int i = lane; i < deg; i += 32) {
        int src = __ldg(&g_csr_src[off + i]);
        float e = __ldg(&g_as[src]) + ad;
        e = (e > 0.f) ? e : NEG_SLOPE * e;
        float ex = __expf(e);
        g_pair[off + i] = make_int2(src, __float_as_int(ex));
        s += ex;
    }
    #pragma unroll
    for (int o = 16; o; o >>= 1) s += __shfl_xor_sync(0xffffffffu, s, o);
    if (lane == 0) g_s[w] = __frcp_rn(s);
}

// ---------------- passC layer 1: aggregate + bias + relu -> bf16 hi/lo -------
__global__ __launch_bounds__(896)
void passC_bf16_kernel(int n, const float* __restrict__ bias) {
    int t = blockIdx.x * 896 + threadIdx.x;
    int d = t / 56;
    int c = t % 56;
    if (d >= n) return;
    size_t base = (size_t)d * KP1 + c * 4;
    if (c >= 50) {
        *(uint2*)(g_ahi + base) = make_uint2(0, 0);
        *(uint2*)(g_alo + base) = make_uint2(0, 0);
        return;
    }
    float rs = __ldg(&g_s[d]);
    int off = g_off[d], deg = g_deg[d];
    float4 acc = __ldg((const float4*)bias + c);
    const float4* h4 = (const float4*)g_h;
    for (int j = 0; j < deg; j++) {
        int2 p = __ldg(&g_pair[off + j]);
        float a = __int_as_float(p.y) * rs;
        float4 v = __ldg(h4 + (size_t)p.x * (OUT_C / 4) + c);
        acc.x = fmaf(a, v.x, acc.x);
        acc.y = fmaf(a, v.y, acc.y);
        acc.z = fmaf(a, v.z, acc.z);
        acc.w = fmaf(a, v.w, acc.w);
    }
    acc.x = fmaxf(acc.x, 0.f); acc.y = fmaxf(acc.y, 0.f);
    acc.z = fmaxf(acc.z, 0.f); acc.w = fmaxf(acc.w, 0.f);
    uint2 uh, ul;
    split4(acc, uh, ul);
    *(uint2*)(g_ahi + base) = uh;
    *(uint2*)(g_alo + base) = ul;
}

// ---------------- passC layer 2: aggregate + bias + relu -> fp32 out ---------
__global__ __launch_bounds__(800)
void passC_f32_kernel(int n, float* __restrict__ out,
                      const float* __restrict__ bias) {
    int t = blockIdx.x * 800 + threadIdx.x;
    int d = t / 50;
    int c = t % 50;
    if (d >= n) return;
    float rs = __ldg(&g_s[d]);
    int off = g_off[d], deg = g_deg[d];
    float4 acc = __ldg((const float4*)bias + c);
    const float4* h4 = (const float4*)g_h;
    for (int j = 0; j < deg; j++) {
        int2 p = __ldg(&g_pair[off + j]);
        float a = __int_as_float(p.y) * rs;
        float4 v = __ldg(h4 + (size_t)p.x * (OUT_C / 4) + c);
        acc.x = fmaf(a, v.x, acc.x);
        acc.y = fmaf(a, v.y, acc.y);
        acc.z = fmaf(a, v.z, acc.z);
        acc.w = fmaf(a, v.w, acc.w);
    }
    acc.x = fmaxf(acc.x, 0.f); acc.y = fmaxf(acc.y, 0.f);
    acc.z = fmaxf(acc.z, 0.f); acc.w = fmaxf(acc.w, 0.f);
    ((float4*)out)[(size_t)d * (OUT_C / 4) + c] = acc;
}

// ---------------- launch -----------------------------------------------------
extern "C" void kernel_launch(void* const* d_in, const int* in_sizes, int n_in,
                              void* d_out, int out_size) {
    const float* x      = (const float*)d_in[0];
    const float* W0     = (const float*)d_in[1];
    const float* a_src0 = (const float*)d_in[2];
    const float* a_dst0 = (const float*)d_in[3];
    const float* b0     = (const float*)d_in[4];
    const float* W1     = (const float*)d_in[5];
    const float* a_src1 = (const float*)d_in[6];
    const float* a_dst1 = (const float*)d_in[7];
    const float* b1     = (const float*)d_in[8];
    const void*  ei     = d_in[9];

    int n    = in_sizes[0] / IN_C;   // 100000
    int E    = in_sizes[9] / 2;      // 1600000
    int Etot = E + n;

    cudaFuncSetAttribute(gemm_tc_kernel<true>,
                         cudaFuncAttributeMaxDynamicSharedMemorySize, GEMM_SMEM);
    cudaFuncSetAttribute(gemm_tc_kernel<false>,
                         cudaFuncAttributeMaxDynamicSharedMemorySize, GEMM_SMEM);

    dim3 gemm_grid(2, (n + 127) / 128);   // x = n-tile (fast), y = m-tile
    int node_blocks  = (n + 255) / 256;
    int edge_blocks  = (Etot + 511) / 512;
    int scan_blocks  = (n + 1023) / 1024;
    int warp_blocks  = (int)(((long long)n * 32 + 255) / 256);
    int aggC1_blocks = (int)(((long long)n * 56 + 895) / 896);
    int aggC2_blocks = (int)(((long long)n * 50 + 799) / 800);

    // ----- layer 1 front (gemm is 4th launch -> ncu capture) -----
    zero_asad_kernel<<<node_blocks, 256>>>(n);
    probe_kernel<<<1, 32>>>((const int*)ei);
    split_w_kernel<<<(NPAD * KP0 + 255) / 256, 256>>>(W0, IN_C, KP0);
    gemm_tc_kernel<true><<<gemm_grid, 256, GEMM_SMEM>>>(
        n, IN_C, IN_C, KP0, KP0 / 32, x, a_src0, a_dst0);

    // ----- CSR build -----
    zero_deg_kernel<<<node_blocks, 256>>>(n);
    hist_kernel<<<edge_blocks, 512>>>(ei, E, Etot);
    scan1_kernel<<<scan_blocks, 1024>>>(n);
    scan2_kernel<<<1, 128>>>(scan_blocks);
    scan3_kernel<<<node_blocks, 256>>>(n);
    fill_kernel<<<edge_blocks, 512>>>(ei, E, Etot);

    // ----- layer 1 back -----
    passAB_kernel<<<warp_blocks, 256>>>(n);
    passC_bf16_kernel<<<aggC1_blocks, 896>>>(n, b0);

    // ----- layer 2 -----
    zero_asad_kernel<<<node_blocks, 256>>>(n);
    split_w_kernel<<<(NPAD * KP1 + 255) / 256, 256>>>(W1, OUT_C, KP1);
    gemm_tc_kernel<false><<<gemm_grid, 256, GEMM_SMEM>>>(
        n, KP1, OUT_C, KP1, KP1 / 32, nullptr, a_src1, a_dst1);
    passAB_kernel<<<warp_blocks, 256>>>(n);
    passC_f32_kernel<<<aggC2_blocks, 800>>>(n, (float*)d_out, b1);
}

// round 16
// speedup vs baseline: 7.1783x; 1.0707x over previous
#include <cuda_runtime.h>
#include <cuda_bf16.h>
#include <cstdint>

#define N_NODES_MAX 100000
#define IN_C 300
#define OUT_C 200
#define E_MAX 1600000
#define ETOT_MAX (E_MAX + N_NODES_MAX)
#define NEG_SLOPE 0.2f

#define KP0 320
#define KP1 224
#define NPAD 256          // padded N for weight tiles (2 x BN=128)
#define SKP 32            // smem k pitch (halves) = 64B rows, swizzled
#define TS (128 * SKP)    // halves per tile array
#define GEMM_SMEM (3 * 4 * TS * 2)  // 3 stages * 4 arrays * TS halves * 2B

// ---------------- scratch ----------------
__device__ float g_h[(size_t)N_NODES_MAX * OUT_C];
__device__ float g_as[N_NODES_MAX];
__device__ float g_ad[N_NODES_MAX];
__device__ float g_s[N_NODES_MAX];
__device__ int   g_idx64;
// CSR
__device__ int   g_deg[N_NODES_MAX];
__device__ int   g_off[N_NODES_MAX + 1];
__device__ int   g_cur[N_NODES_MAX];
__device__ int   g_bsum[256];
__device__ int   g_boff[257];
__device__ int   g_csr_src[ETOT_MAX];
__device__ int2  g_pair[ETOT_MAX];    // {src, float_bits(exp_e)} for passC
// bf16 split buffers (layer-2 A written by passC; weights per layer)
__device__ __nv_bfloat16 g_ahi[(size_t)N_NODES_MAX * KP1];
__device__ __nv_bfloat16 g_alo[(size_t)N_NODES_MAX * KP1];
__device__ __nv_bfloat16 g_whi[(size_t)NPAD * KP0];
__device__ __nv_bfloat16 g_wlo[(size_t)NPAD * KP0];

// ---------------- helpers ----------------
__device__ __forceinline__ int edge_at(const void* ei, int is64, long long pos) {
    if (is64) return (int)((const long long*)ei)[pos];
    return ((const int*)ei)[pos];
}

__device__ __forceinline__ uint32_t smem_u32(const void* p) {
    return (uint32_t)__cvta_generic_to_shared(p);
}

__device__ __forceinline__ void cp16(uint32_t dst, const void* src, bool pred) {
    int sz = pred ? 16 : 0;
    asm volatile("cp.async.cg.shared.global [%0], [%1], 16, %2;"
                 :: "r"(dst), "l"(src), "r"(sz));
}

#define CP_COMMIT() asm volatile("cp.async.commit_group;")
#define CP_WAIT(N)  asm volatile("cp.async.wait_group %0;" :: "n"(N))

#define LDSM_X4(r0, r1, r2, r3, addr)                                        \
    asm volatile("ldmatrix.sync.aligned.m8n8.x4.shared.b16 {%0,%1,%2,%3}, [%4];" \
                 : "=r"(r0), "=r"(r1), "=r"(r2), "=r"(r3) : "r"(addr))

#define MMA_BF16(d, a, b)                                                    \
    asm volatile("mma.sync.aligned.m16n8k16.row.col.f32.bf16.bf16.f32 "      \
                 "{%0,%1,%2,%3},{%4,%5,%6,%7},{%8,%9},{%0,%1,%2,%3};"        \
                 : "+f"(d[0]), "+f"(d[1]), "+f"(d[2]), "+f"(d[3])            \
                 : "r"(a[0]), "r"(a[1]), "r"(a[2]), "r"(a[3]),               \
                   "r"(b[0]), "r"(b[1]))

// swizzled half-index within a tile: row pitch 32 halves (64B),
// 16B chunk (8 halves) XOR'd with row bits to avoid ldmatrix bank conflicts.
__device__ __forceinline__ int swz8(int row, int chunk) {
    return row * 32 + ((chunk ^ ((row >> 1) & 3)) << 3);
}

__device__ __forceinline__ void bf16_split(float v, __nv_bfloat16& hi, __nv_bfloat16& lo) {
    hi = __float2bfloat16(v);
    lo = __float2bfloat16(v - __bfloat162float(hi));
}

// split a float4 into packed hi (uint2) and lo (uint2) bf16x4
__device__ __forceinline__ void split4(float4 v, uint2& uh, uint2& ul) {
    __nv_bfloat162 h01 = __floats2bfloat162_rn(v.x, v.y);
    __nv_bfloat162 h23 = __floats2bfloat162_rn(v.z, v.w);
    float2 f01 = __bfloat1622float2(h01);
    float2 f23 = __bfloat1622float2(h23);
    __nv_bfloat162 l01 = __floats2bfloat162_rn(v.x - f01.x, v.y - f01.y);
    __nv_bfloat162 l23 = __floats2bfloat162_rn(v.z - f23.x, v.w - f23.y);
    uh.x = *(uint32_t*)&h01; uh.y = *(uint32_t*)&h23;
    ul.x = *(uint32_t*)&l01; ul.y = *(uint32_t*)&l23;
}

__global__ void probe_kernel(const int* ei) {
    if (threadIdx.x == 0 && blockIdx.x == 0) {
        int is64 = 1;
        #pragma unroll
        for (int i = 1; i < 32; i += 2)
            if (ei[i] != 0) { is64 = 0; break; }
        g_idx64 = is64;
    }
}

__global__ void zero_asad_kernel(int n) {
    int i = blockIdx.x * blockDim.x + threadIdx.x;
    if (i < n) { g_as[i] = 0.f; g_ad[i] = 0.f; }
}

// ---------------- CSR build --------------------------------------------------
__global__ void zero_deg_kernel(int n) {
    int i = blockIdx.x * blockDim.x + threadIdx.x;
    if (i < n) g_deg[i] = 0;
}

__global__ void hist_kernel(const void* __restrict__ ei, int E, int Etot) {
    int i = blockIdx.x * blockDim.x + threadIdx.x;
    if (i >= Etot) return;
    int is64 = g_idx64;
    int dst = (i < E) ? edge_at(ei, is64, (long long)E + i) : (i - E);
    atomicAdd(&g_deg[dst], 1);
}

__global__ __launch_bounds__(1024) void scan1_kernel(int n) {
    __shared__ int sh[1024];
    int t = threadIdx.x;
    int i = blockIdx.x * 1024 + t;
    int v = (i < n) ? g_deg[i] : 0;
    sh[t] = v;
    __syncthreads();
    #pragma unroll
    for (int o = 1; o < 1024; o <<= 1) {
        int u = (t >= o) ? sh[t - o] : 0;
        __syncthreads();
        sh[t] += u;
        __syncthreads();
    }
    if (i < n) g_off[i] = sh[t] - v;
    if (t == 1023) g_bsum[blockIdx.x] = sh[1023];
}

__global__ __launch_bounds__(128) void scan2_kernel(int nb) {
    __shared__ int sh[128];
    int t = threadIdx.x;
    int v = (t < nb) ? g_bsum[t] : 0;
    sh[t] = v;
    __syncthreads();
    #pragma unroll
    for (int o = 1; o < 128; o <<= 1) {
        int u = (t >= o) ? sh[t - o] : 0;
        __syncthreads();
        sh[t] += u;
        __syncthreads();
    }
    g_boff[t] = sh[t] - v;
    if (t == 127) g_boff[128] = sh[127];
}

__global__ void scan3_kernel(int n) {
    int i = blockIdx.x * blockDim.x + threadIdx.x;
    if (i < n) {
        int o = g_off[i] + g_boff[i >> 10];
        g_off[i] = o;
        g_cur[i] = o;
    }
    if (i == 0) g_off[n] = g_boff[128];
}

__global__ void fill_kernel(const void* __restrict__ ei, int E, int Etot) {
    int i = blockIdx.x * blockDim.x + threadIdx.x;
    if (i >= Etot) return;
    int is64 = g_idx64;
    int src, dst;
    if (i < E) {
        src = edge_at(ei, is64, i);
        dst = edge_at(ei, is64, (long long)E + i);
    } else {
        src = dst = i - E;
    }
    int pos = atomicAdd(&g_cur[dst], 1);
    g_csr_src[pos] = src;
}

// ---------------- split W -----------------------------------------------------
__global__ void split_w_kernel(const float* __restrict__ W, int K, int KP) {
    int idx = blockIdx.x * blockDim.x + threadIdx.x;
    if (idx >= NPAD * KP) return;
    int k = idx % KP;
    int n = idx / KP;
    float v = (k < K && n < OUT_C) ? W[(size_t)k * OUT_C + n] : 0.f;
    __nv_bfloat16 hi, lo;
    bf16_split(v, hi, lo);
    g_whi[idx] = hi;
    g_wlo[idx] = lo;
}

// ---------------- tensor-core GEMM + fused alpha epilogue --------------------
// BM=128, BN=128, 8 warps (2m x 4n), warp tile 64x32. 2 CTAs/SM enforced.
// 3-stage cp.async pipeline, ONE __syncthreads per K-step, swizzled 64B-pitch
// smem. Grid: (2, m_tiles) — x = n-tile fast axis for L2 A reuse.
// AFP32: A loaded as fp32 (layer-1 x), split to bf16 hi/lo in-register.
// !AFP32: A loaded from g_ahi/g_alo via cp.async (layer 2).
template<bool AFP32>
__global__ __launch_bounds__(256, 2)
void gemm_tc_kernel(int M, int ldaA, int Kin, int ldaB, int kblocks,
                    const float* __restrict__ Afp,
                    const float* __restrict__ a_src,
                    const float* __restrict__ a_dst) {
    extern __shared__ __nv_bfloat16 smem[];

    int tid = threadIdx.x;
    int lane = tid & 31, warp = tid >> 5;
    int wm = warp & 1, wn = warp >> 1;
    int bm = blockIdx.y * 128;          // m-tile (slow axis)
    int n0 = blockIdx.x * 128;          // n-tile (fast axis -> L2 A reuse)

    float acc[4][4][4];
    #pragma unroll
    for (int i = 0; i < 4; i++)
        #pragma unroll
        for (int j = 0; j < 4; j++)
            #pragma unroll
            for (int q = 0; q < 4; q++) acc[i][j][q] = 0.f;

    int a_r = lane & 15, a_c = (lane >> 4) << 3;
    int b_r = (lane & 7) + ((lane >> 4) << 3);
    int b_c = ((lane >> 3) & 1) << 3;

    auto load_stage = [&](int kb, int s) {
        __nv_bfloat16* sAh = smem + s * 4 * TS;
        __nv_bfloat16* sAl = sAh + TS;
        __nv_bfloat16* sBh = sAl + TS;
        __nv_bfloat16* sBl = sBh + TS;
        if (AFP32) {
            // A: 128 rows x 32 floats = 1024 float4 loads over 256 threads
            #pragma unroll
            for (int i = 0; i < 4; i++) {
                int idx = tid + i * 256;
                int row = idx >> 3, qf = idx & 7;   // qf = 4-half (8B) unit
                int gk = kb * 32 + qf * 4;
                float4 f = make_float4(0.f, 0.f, 0.f, 0.f);
                if ((bm + row) < M && (gk + 4) <= Kin)
                    f = *(const float4*)(Afp + (size_t)(bm + row) * ldaA + gk);
                uint2 uh, ul;
                split4(f, uh, ul);
                int o = swz8(row, qf >> 1) + ((qf & 1) << 2);
                *(uint2*)(sAh + o) = uh;
                *(uint2*)(sAl + o) = ul;
            }
        } else {
            extern __device__ __nv_bfloat16 g_ahi[], g_alo[];
            #pragma unroll
            for (int i = 0; i < 2; i++) {
                int idx = tid + i * 256;
                int row = idx >> 2, q = idx & 3;    // q = 16B chunk
                bool vA = (bm + row) < M;
                int rA = vA ? (bm + row) : 0;
                size_t offA = (size_t)rA * ldaA + kb * 32 + q * 8;
                int o = swz8(row, q);
                cp16(smem_u32(sAh + o), g_ahi + offA, vA);
                cp16(smem_u32(sAl + o), g_alo + offA, vA);
            }
        }
        #pragma unroll
        for (int i = 0; i < 2; i++) {
            int idx = tid + i * 256;
            int row = idx >> 2, q = idx & 3;
            size_t offB = (size_t)(n0 + row) * ldaB + kb * 32 + q * 8;
            int o = swz8(row, q);
            cp16(smem_u32(sBh + o), g_whi + offB, true);
            cp16(smem_u32(sBl + o), g_wlo + offB, true);
        }
        CP_COMMIT();
    };

    auto compute = [&](int s) {
        __nv_bfloat16* sAh = smem + s * 4 * TS;
        __nv_bfloat16* sAl = sAh + TS;
        __nv_bfloat16* sBh = sAl + TS;
        __nv_bfloat16* sBl = sBh + TS;
        #pragma unroll
        for (int ks = 0; ks < 2; ks++) {
            int kh = ks * 16;
            uint32_t ah[4][4], al[4][4], bh[4][2], bl[4][2];
            #pragma unroll
            for (int mi = 0; mi < 4; mi++) {
                int row = wm * 64 + mi * 16 + a_r;
                int o = swz8(row, (kh + a_c) >> 3);
                uint32_t ad = smem_u32(sAh + o);
                LDSM_X4(ah[mi][0], ah[mi][1], ah[mi][2], ah[mi][3], ad);
                ad = smem_u32(sAl + o);
                LDSM_X4(al[mi][0], al[mi][1], al[mi][2], al[mi][3], ad);
            }
            #pragma unroll
            for (int nj = 0; nj < 2; nj++) {
                int row = wn * 32 + nj * 16 + b_r;
                int o = swz8(row, (kh + b_c) >> 3);
                uint32_t ad = smem_u32(sBh + o);
                LDSM_X4(bh[2 * nj][0], bh[2 * nj][1], bh[2 * nj + 1][0], bh[2 * nj + 1][1], ad);
                ad = smem_u32(sBl + o);
                LDSM_X4(bl[2 * nj][0], bl[2 * nj][1], bl[2 * nj + 1][0], bl[2 * nj + 1][1], ad);
            }
            #pragma unroll
            for (int mi = 0; mi < 4; mi++)
                #pragma unroll
                for (int ni = 0; ni < 4; ni++) {
                    MMA_BF16(acc[mi][ni], ah[mi], bh[ni]);
                    MMA_BF16(acc[mi][ni], ah[mi], bl[ni]);
                    MMA_BF16(acc[mi][ni], al[mi], bh[ni]);
                }
        }
    };

    load_stage(0, 0);
    if (kblocks > 1) load_stage(1, 1);

    for (int kb = 0; kb < kblocks; kb++) {
        CP_WAIT(1);                 // stage kb complete (kb+1 may be pending)
        __syncthreads();            // single barrier per K-step
        compute(kb % 3);
        if (kb + 2 < kblocks)
            load_stage(kb + 2, (kb + 2) % 3);  // overwrites stage (kb-1)%3: safe
    }

    float vs0[4], vs1[4], vd0[4], vd1[4];
    #pragma unroll
    for (int ni = 0; ni < 4; ni++) {
        int c = n0 + wn * 32 + ni * 8 + ((lane & 3) << 1);
        vs0[ni] = (c < OUT_C) ? __ldg(a_src + c) : 0.f;
        vs1[ni] = (c + 1 < OUT_C) ? __ldg(a_src + c + 1) : 0.f;
        vd0[ni] = (c < OUT_C) ? __ldg(a_dst + c) : 0.f;
        vd1[ni] = (c + 1 < OUT_C) ? __ldg(a_dst + c + 1) : 0.f;
    }

    #pragma unroll
    for (int mi = 0; mi < 4; mi++) {
        int r = bm + wm * 64 + mi * 16 + (lane >> 2);
        #pragma unroll
        for (int ni = 0; ni < 4; ni++) {
            int c = n0 + wn * 32 + ni * 8 + ((lane & 3) << 1);
            if (c >= OUT_C) continue;
            if (r < M)
                *(float2*)(g_h + (size_t)r * OUT_C + c) =
                    make_float2(acc[mi][ni][0], acc[mi][ni][1]);
            if (r + 8 < M)
                *(float2*)(g_h + (size_t)(r + 8) * OUT_C + c) =
                    make_float2(acc[mi][ni][2], acc[mi][ni][3]);
        }
        float ps0 = 0.f, pd0 = 0.f, ps1 = 0.f, pd1 = 0.f;
        #pragma unroll
        for (int ni = 0; ni < 4; ni++) {
            ps0 += acc[mi][ni][0] * vs0[ni] + acc[mi][ni][1] * vs1[ni];
            pd0 += acc[mi][ni][0] * vd0[ni] + acc[mi][ni][1] * vd1[ni];
            ps1 += acc[mi][ni][2] * vs0[ni] + acc[mi][ni][3] * vs1[ni];
            pd1 += acc[mi][ni][2] * vd0[ni] + acc[mi][ni][3] * vd1[ni];
        }
        #pragma unroll
        for (int o = 1; o <= 2; o <<= 1) {
            ps0 += __shfl_xor_sync(0xffffffffu, ps0, o);
            pd0 += __shfl_xor_sync(0xffffffffu, pd0, o);
            ps1 += __shfl_xor_sync(0xffffffffu, ps1, o);
            pd1 += __shfl_xor_sync(0xffffffffu, pd1, o);
        }
        if ((lane & 3) == 0) {
            if (r < M) { atomicAdd(&g_as[r], ps0); atomicAdd(&g_ad[r], pd0); }
            if (r + 8 < M) { atomicAdd(&g_as[r + 8], ps1); atomicAdd(&g_ad[r + 8], pd1); }
        }
    }
}

// ---------------- fused passAB: warp per dst; e + exp + segment sum ----------
// Writes packed {src, exp_e} records for passC.
__global__ void passAB_kernel(int n) {
    int w = (int)((blockIdx.x * (size_t)blockDim.x + threadIdx.x) >> 5);
    int lane = threadIdx.x & 31;
    if (w >= n) return;
    int off = g_off[w], deg = g_deg[w];
    float ad = __ldg(&g_ad[w]);
    float s = 0.f;
    for (int i = lane; i < deg; i += 32) {
        int src = __ldg(&g_csr_src[off + i]);
        float e = __ldg(&g_as[src]) + ad;
        e = (e > 0.f) ? e : NEG_SLOPE * e;
        float ex = __expf(e);
        g_pair[off + i] = make_int2(src, __float_as_int(ex));
        s += ex;
    }
    #pragma unroll
    for (int o = 16; o; o >>= 1) s += __shfl_xor_sync(0xffffffffu, s, o);
    if (lane == 0) g_s[w] = __frcp_rn(s);
}

// ---------------- passC layer 1: aggregate + bias + relu -> bf16 hi/lo -------
__global__ __launch_bounds__(896)
void passC_bf16_kernel(int n, const float* __restrict__ bias) {
    int t = blockIdx.x * 896 + threadIdx.x;
    int d = t / 56;
    int c = t % 56;
    if (d >= n) return;
    size_t base = (size_t)d * KP1 + c * 4;
    if (c >= 50) {
        *(uint2*)(g_ahi + base) = make_uint2(0, 0);
        *(uint2*)(g_alo + base) = make_uint2(0, 0);
        return;
    }
    float rs = __ldg(&g_s[d]);
    int off = g_off[d], deg = g_deg[d];
    float4 acc = __ldg((const float4*)bias + c);
    const float4* h4 = (const float4*)g_h;
    for (int j = 0; j < deg; j++) {
        int2 p = __ldg(&g_pair[off + j]);
        float a = __int_as_float(p.y) * rs;
        float4 v = __ldg(h4 + (size_t)p.x * (OUT_C / 4) + c);
        acc.x = fmaf(a, v.x, acc.x);
        acc.y = fmaf(a, v.y, acc.y);
        acc.z = fmaf(a, v.z, acc.z);
        acc.w = fmaf(a, v.w, acc.w);
    }
    acc.x = fmaxf(acc.x, 0.f); acc.y = fmaxf(acc.y, 0.f);
    acc.z = fmaxf(acc.z, 0.f); acc.w = fmaxf(acc.w, 0.f);
    uint2 uh, ul;
    split4(acc, uh, ul);
    *(uint2*)(g_ahi + base) = uh;
    *(uint2*)(g_alo + base) = ul;
}

// ---------------- passC layer 2: aggregate + bias + relu -> fp32 out ---------
__global__ __launch_bounds__(800)
void passC_f32_kernel(int n, float* __restrict__ out,
                      const float* __restrict__ bias) {
    int t = blockIdx.x * 800 + threadIdx.x;
    int d = t / 50;
    int c = t % 50;
    if (d >= n) return;
    float rs = __ldg(&g_s[d]);
    int off = g_off[d], deg = g_deg[d];
    float4 acc = __ldg((const float4*)bias + c);
    const float4* h4 = (const float4*)g_h;
    for (int j = 0; j < deg; j++) {
        int2 p = __ldg(&g_pair[off + j]);
        float a = __int_as_float(p.y) * rs;
        float4 v = __ldg(h4 + (size_t)p.x * (OUT_C / 4) + c);
        acc.x = fmaf(a, v.x, acc.x);
        acc.y = fmaf(a, v.y, acc.y);
        acc.z = fmaf(a, v.z, acc.z);
        acc.w = fmaf(a, v.w, acc.w);
    }
    acc.x = fmaxf(acc.x, 0.f); acc.y = fmaxf(acc.y, 0.f);
    acc.z = fmaxf(acc.z, 0.f); acc.w = fmaxf(acc.w, 0.f);
    ((float4*)out)[(size_t)d * (OUT_C / 4) + c] = acc;
}

// ---------------- launch -----------------------------------------------------
extern "C" void kernel_launch(void* const* d_in, const int* in_sizes, int n_in,
                              void* d_out, int out_size) {
    const float* x      = (const float*)d_in[0];
    const float* W0     = (const float*)d_in[1];
    const float* a_src0 = (const float*)d_in[2];
    const float* a_dst0 = (const float*)d_in[3];
    const float* b0     = (const float*)d_in[4];
    const float* W1     = (const float*)d_in[5];
    const float* a_src1 = (const float*)d_in[6];
    const float* a_dst1 = (const float*)d_in[7];
    const float* b1     = (const float*)d_in[8];
    const void*  ei     = d_in[9];

    int n    = in_sizes[0] / IN_C;   // 100000
    int E    = in_sizes[9] / 2;      // 1600000
    int Etot = E + n;

    cudaFuncSetAttribute(gemm_tc_kernel<true>,
                         cudaFuncAttributeMaxDynamicSharedMemorySize, GEMM_SMEM);
    cudaFuncSetAttribute(gemm_tc_kernel<false>,
                         cudaFuncAttributeMaxDynamicSharedMemorySize, GEMM_SMEM);

    dim3 gemm_grid(2, (n + 127) / 128);   // x = n-tile (fast), y = m-tile
    int node_blocks  = (n + 255) / 256;
    int edge_blocks  = (Etot + 511) / 512;
    int scan_blocks  = (n + 1023) / 1024;
    int warp_blocks  = (int)(((long long)n * 32 + 255) / 256);
    int aggC1_blocks = (int)(((long long)n * 56 + 895) / 896);
    int aggC2_blocks = (int)(((long long)n * 50 + 799) / 800);

    // ----- layer 1 front (gemm is 4th launch -> ncu capture) -----
    zero_asad_kernel<<<node_blocks, 256>>>(n);
    probe_kernel<<<1, 32>>>((const int*)ei);
    split_w_kernel<<<(NPAD * KP0 + 255) / 256, 256>>>(W0, IN_C, KP0);
    gemm_tc_kernel<true><<<gemm_grid, 256, GEMM_SMEM>>>(
        n, IN_C, IN_C, KP0, KP0 / 32, x, a_src0, a_dst0);

    // ----- CSR build -----
    zero_deg_kernel<<<node_blocks, 256>>>(n);
    hist_kernel<<<edge_blocks, 512>>>(ei, E, Etot);
    scan1_kernel<<<scan_blocks, 1024>>>(n);
    scan2_kernel<<<1, 128>>>(scan_blocks);
    scan3_kernel<<<node_blocks, 256>>>(n);
    fill_kernel<<<edge_blocks, 512>>>(ei, E, Etot);

    // ----- layer 1 back -----
    passAB_kernel<<<warp_blocks, 256>>>(n);
    passC_bf16_kernel<<<aggC1_blocks, 896>>>(n, b0);

    // ----- layer 2 -----
    zero_asad_kernel<<<node_blocks, 256>>>(n);
    split_w_kernel<<<(NPAD * KP1 + 255) / 256, 256>>>(W1, OUT_C, KP1);
    gemm_tc_kernel<false><<<gemm_grid, 256, GEMM_SMEM>>>(
        n, KP1, OUT_C, KP1, KP1 / 32, nullptr, a_src1, a_dst1);
    passAB_kernel<<<warp_blocks, 256>>>(n);
    passC_f32_kernel<<<aggC2_blocks, 800>>>(n, (float*)d_out, b1);
}

// round 17
// speedup vs baseline: 7.7854x; 1.0846x over previous
#include <cuda_runtime.h>
#include <cuda_bf16.h>
#include <cstdint>

#define N_NODES_MAX 100000
#define IN_C 300
#define OUT_C 200
#define E_MAX 1600000
#define ETOT_MAX (E_MAX + N_NODES_MAX)
#define NEG_SLOPE 0.2f

#define KP0 320
#define KP1 224
#define NPAD 256          // padded N for weight tiles (2 x BN=128)
#define SKP 32            // smem k pitch (halves) = 64B rows, swizzled
#define TS (128 * SKP)    // halves per tile array
#define GEMM_SMEM (3 * 4 * TS * 2)  // 3 stages * 4 arrays * TS halves * 2B

// ---------------- scratch ----------------
__device__ float g_h[(size_t)N_NODES_MAX * OUT_C];
__device__ float g_as[N_NODES_MAX];
__device__ float g_ad[N_NODES_MAX];
__device__ float g_s[N_NODES_MAX];
__device__ int   g_idx64;
// CSR
__device__ int   g_deg[N_NODES_MAX];
__device__ int   g_off[N_NODES_MAX + 1];
__device__ int   g_cur[N_NODES_MAX];
__device__ int   g_bsum[256];
__device__ int   g_boff[257];
__device__ int   g_csr_src[ETOT_MAX];
__device__ int2  g_pair[ETOT_MAX];    // {src, float_bits(exp_e)} for passC
// bf16 split buffers (layer-2 A written by passC; weights per layer)
__device__ __nv_bfloat16 g_ahi[(size_t)N_NODES_MAX * KP1];
__device__ __nv_bfloat16 g_alo[(size_t)N_NODES_MAX * KP1];
__device__ __nv_bfloat16 g_whi[(size_t)NPAD * KP0];
__device__ __nv_bfloat16 g_wlo[(size_t)NPAD * KP0];

// ---------------- helpers ----------------
__device__ __forceinline__ int edge_at(const void* ei, int is64, long long pos) {
    if (is64) return (int)((const long long*)ei)[pos];
    return ((const int*)ei)[pos];
}

__device__ __forceinline__ uint32_t smem_u32(const void* p) {
    return (uint32_t)__cvta_generic_to_shared(p);
}

__device__ __forceinline__ void cp16(uint32_t dst, const void* src, bool pred) {
    int sz = pred ? 16 : 0;
    asm volatile("cp.async.cg.shared.global [%0], [%1], 16, %2;"
                 :: "r"(dst), "l"(src), "r"(sz));
}

#define CP_COMMIT() asm volatile("cp.async.commit_group;")
#define CP_WAIT(N)  asm volatile("cp.async.wait_group %0;" :: "n"(N))

#define LDSM_X4(r0, r1, r2, r3, addr)                                        \
    asm volatile("ldmatrix.sync.aligned.m8n8.x4.shared.b16 {%0,%1,%2,%3}, [%4];" \
                 : "=r"(r0), "=r"(r1), "=r"(r2), "=r"(r3) : "r"(addr))

#define MMA_BF16(d, a, b)                                                    \
    asm volatile("mma.sync.aligned.m16n8k16.row.col.f32.bf16.bf16.f32 "      \
                 "{%0,%1,%2,%3},{%4,%5,%6,%7},{%8,%9},{%0,%1,%2,%3};"        \
                 : "+f"(d[0]), "+f"(d[1]), "+f"(d[2]), "+f"(d[3])            \
                 : "r"(a[0]), "r"(a[1]), "r"(a[2]), "r"(a[3]),               \
                   "r"(b[0]), "r"(b[1]))

// swizzled half-index within a tile: row pitch 32 halves (64B),
// 16B chunk (8 halves) XOR'd with row bits to avoid ldmatrix bank conflicts.
__device__ __forceinline__ int swz8(int row, int chunk) {
    return row * 32 + ((chunk ^ ((row >> 1) & 3)) << 3);
}

__device__ __forceinline__ void bf16_split(float v, __nv_bfloat16& hi, __nv_bfloat16& lo) {
    hi = __float2bfloat16(v);
    lo = __float2bfloat16(v - __bfloat162float(hi));
}

// split a float4 into packed hi (uint2) and lo (uint2) bf16x4
__device__ __forceinline__ void split4(float4 v, uint2& uh, uint2& ul) {
    __nv_bfloat162 h01 = __floats2bfloat162_rn(v.x, v.y);
    __nv_bfloat162 h23 = __floats2bfloat162_rn(v.z, v.w);
    float2 f01 = __bfloat1622float2(h01);
    float2 f23 = __bfloat1622float2(h23);
    __nv_bfloat162 l01 = __floats2bfloat162_rn(v.x - f01.x, v.y - f01.y);
    __nv_bfloat162 l23 = __floats2bfloat162_rn(v.z - f23.x, v.w - f23.y);
    uh.x = *(uint32_t*)&h01; uh.y = *(uint32_t*)&h23;
    ul.x = *(uint32_t*)&l01; ul.y = *(uint32_t*)&l23;
}

__global__ void probe_kernel(const int* ei) {
    if (threadIdx.x == 0 && blockIdx.x == 0) {
        int is64 = 1;
        #pragma unroll
        for (int i = 1; i < 32; i += 2)
            if (ei[i] != 0) { is64 = 0; break; }
        g_idx64 = is64;
    }
}

__global__ void zero_asad_kernel(int n) {
    int i = blockIdx.x * blockDim.x + threadIdx.x;
    if (i < n) { g_as[i] = 0.f; g_ad[i] = 0.f; }
}

// ---------------- CSR build --------------------------------------------------
__global__ void zero_deg_kernel(int n) {
    int i = blockIdx.x * blockDim.x + threadIdx.x;
    if (i < n) g_deg[i] = 0;
}

__global__ void hist_kernel(const void* __restrict__ ei, int E, int Etot) {
    int i = blockIdx.x * blockDim.x + threadIdx.x;
    if (i >= Etot) return;
    int is64 = g_idx64;
    int dst = (i < E) ? edge_at(ei, is64, (long long)E + i) : (i - E);
    atomicAdd(&g_deg[dst], 1);
}

__global__ __launch_bounds__(1024) void scan1_kernel(int n) {
    __shared__ int sh[1024];
    int t = threadIdx.x;
    int i = blockIdx.x * 1024 + t;
    int v = (i < n) ? g_deg[i] : 0;
    sh[t] = v;
    __syncthreads();
    #pragma unroll
    for (int o = 1; o < 1024; o <<= 1) {
        int u = (t >= o) ? sh[t - o] : 0;
        __syncthreads();
        sh[t] += u;
        __syncthreads();
    }
    if (i < n) g_off[i] = sh[t] - v;
    if (t == 1023) g_bsum[blockIdx.x] = sh[1023];
}

__global__ __launch_bounds__(128) void scan2_kernel(int nb) {
    __shared__ int sh[128];
    int t = threadIdx.x;
    int v = (t < nb) ? g_bsum[t] : 0;
    sh[t] = v;
    __syncthreads();
    #pragma unroll
    for (int o = 1; o < 128; o <<= 1) {
        int u = (t >= o) ? sh[t - o] : 0;
        __syncthreads();
        sh[t] += u;
        __syncthreads();
    }
    g_boff[t] = sh[t] - v;
    if (t == 127) g_boff[128] = sh[127];
}

__global__ void scan3_kernel(int n) {
    int i = blockIdx.x * blockDim.x + threadIdx.x;
    if (i < n) {
        int o = g_off[i] + g_boff[i >> 10];
        g_off[i] = o;
        g_cur[i] = o;
    }
    if (i == 0) g_off[n] = g_boff[128];
}

__global__ void fill_kernel(const void* __restrict__ ei, int E, int Etot) {
    int i = blockIdx.x * blockDim.x + threadIdx.x;
    if (i >= Etot) return;
    int is64 = g_idx64;
    int src, dst;
    if (i < E) {
        src = edge_at(ei, is64, i);
        dst = edge_at(ei, is64, (long long)E + i);
    } else {
        src = dst = i - E;
    }
    int pos = atomicAdd(&g_cur[dst], 1);
    g_csr_src[pos] = src;
}

// ---------------- split W -----------------------------------------------------
__global__ void split_w_kernel(const float* __restrict__ W, int K, int KP) {
    int idx = blockIdx.x * blockDim.x + threadIdx.x;
    if (idx >= NPAD * KP) return;
    int k = idx % KP;
    int n = idx / KP;
    float v = (k < K && n < OUT_C) ? W[(size_t)k * OUT_C + n] : 0.f;
    __nv_bfloat16 hi, lo;
    bf16_split(v, hi, lo);
    g_whi[idx] = hi;
    g_wlo[idx] = lo;
}

// ---------------- tensor-core GEMM + fused alpha epilogue --------------------
// BM=128, BN=128, 8 warps (2m x 4n), warp tile 64x32. 2 CTAs/SM enforced.
// 3-stage cp.async pipeline, ONE __syncthreads per K-step, swizzled 64B-pitch
// smem. Grid: (2, m_tiles) — x = n-tile fast axis for L2 A reuse.
template<bool AFP32>
__global__ __launch_bounds__(256, 2)
void gemm_tc_kernel(int M, int ldaA, int Kin, int ldaB, int kblocks,
                    const float* __restrict__ Afp,
                    const float* __restrict__ a_src,
                    const float* __restrict__ a_dst) {
    extern __shared__ __nv_bfloat16 smem[];

    int tid = threadIdx.x;
    int lane = tid & 31, warp = tid >> 5;
    int wm = warp & 1, wn = warp >> 1;
    int bm = blockIdx.y * 128;          // m-tile (slow axis)
    int n0 = blockIdx.x * 128;          // n-tile (fast axis -> L2 A reuse)

    float acc[4][4][4];
    #pragma unroll
    for (int i = 0; i < 4; i++)
        #pragma unroll
        for (int j = 0; j < 4; j++)
            #pragma unroll
            for (int q = 0; q < 4; q++) acc[i][j][q] = 0.f;

    int a_r = lane & 15, a_c = (lane >> 4) << 3;
    int b_r = (lane & 7) + ((lane >> 4) << 3);
    int b_c = ((lane >> 3) & 1) << 3;

    auto load_stage = [&](int kb, int s) {
        __nv_bfloat16* sAh = smem + s * 4 * TS;
        __nv_bfloat16* sAl = sAh + TS;
        __nv_bfloat16* sBh = sAl + TS;
        __nv_bfloat16* sBl = sBh + TS;
        if (AFP32) {
            #pragma unroll
            for (int i = 0; i < 4; i++) {
                int idx = tid + i * 256;
                int row = idx >> 3, qf = idx & 7;
                int gk = kb * 32 + qf * 4;
                float4 f = make_float4(0.f, 0.f, 0.f, 0.f);
                if ((bm + row) < M && (gk + 4) <= Kin)
                    f = *(const float4*)(Afp + (size_t)(bm + row) * ldaA + gk);
                uint2 uh, ul;
                split4(f, uh, ul);
                int o = swz8(row, qf >> 1) + ((qf & 1) << 2);
                *(uint2*)(sAh + o) = uh;
                *(uint2*)(sAl + o) = ul;
            }
        } else {
            extern __device__ __nv_bfloat16 g_ahi[], g_alo[];
            #pragma unroll
            for (int i = 0; i < 2; i++) {
                int idx = tid + i * 256;
                int row = idx >> 2, q = idx & 3;
                bool vA = (bm + row) < M;
                int rA = vA ? (bm + row) : 0;
                size_t offA = (size_t)rA * ldaA + kb * 32 + q * 8;
                int o = swz8(row, q);
                cp16(smem_u32(sAh + o), g_ahi + offA, vA);
                cp16(smem_u32(sAl + o), g_alo + offA, vA);
            }
        }
        #pragma unroll
        for (int i = 0; i < 2; i++) {
            int idx = tid + i * 256;
            int row = idx >> 2, q = idx & 3;
            size_t offB = (size_t)(n0 + row) * ldaB + kb * 32 + q * 8;
            int o = swz8(row, q);
            cp16(smem_u32(sBh + o), g_whi + offB, true);
            cp16(smem_u32(sBl + o), g_wlo + offB, true);
        }
        CP_COMMIT();
    };

    auto compute = [&](int s) {
        __nv_bfloat16* sAh = smem + s * 4 * TS;
        __nv_bfloat16* sAl = sAh + TS;
        __nv_bfloat16* sBh = sAl + TS;
        __nv_bfloat16* sBl = sBh + TS;
        #pragma unroll
        for (int ks = 0; ks < 2; ks++) {
            int kh = ks * 16;
            uint32_t ah[4][4], al[4][4], bh[4][2], bl[4][2];
            #pragma unroll
            for (int mi = 0; mi < 4; mi++) {
                int row = wm * 64 + mi * 16 + a_r;
                int o = swz8(row, (kh + a_c) >> 3);
                uint32_t ad = smem_u32(sAh + o);
                LDSM_X4(ah[mi][0], ah[mi][1], ah[mi][2], ah[mi][3], ad);
                ad = smem_u32(sAl + o);
                LDSM_X4(al[mi][0], al[mi][1], al[mi][2], al[mi][3], ad);
            }
            #pragma unroll
            for (int nj = 0; nj < 2; nj++) {
                int row = wn * 32 + nj * 16 + b_r;
                int o = swz8(row, (kh + b_c) >> 3);
                uint32_t ad = smem_u32(sBh + o);
                LDSM_X4(bh[2 * nj][0], bh[2 * nj][1], bh[2 * nj + 1][0], bh[2 * nj + 1][1], ad);
                ad = smem_u32(sBl + o);
                LDSM_X4(bl[2 * nj][0], bl[2 * nj][1], bl[2 * nj + 1][0], bl[2 * nj + 1][1], ad);
            }
            #pragma unroll
            for (int mi = 0; mi < 4; mi++)
                #pragma unroll
                for (int ni = 0; ni < 4; ni++) {
                    MMA_BF16(acc[mi][ni], ah[mi], bh[ni]);
                    MMA_BF16(acc[mi][ni], ah[mi], bl[ni]);
                    MMA_BF16(acc[mi][ni], al[mi], bh[ni]);
                }
        }
    };

    load_stage(0, 0);
    if (kblocks > 1) load_stage(1, 1);

    for (int kb = 0; kb < kblocks; kb++) {
        CP_WAIT(1);
        __syncthreads();
        compute(kb % 3);
        if (kb + 2 < kblocks)
            load_stage(kb + 2, (kb + 2) % 3);
    }

    float vs0[4], vs1[4], vd0[4], vd1[4];
    #pragma unroll
    for (int ni = 0; ni < 4; ni++) {
        int c = n0 + wn * 32 + ni * 8 + ((lane & 3) << 1);
        vs0[ni] = (c < OUT_C) ? __ldg(a_src + c) : 0.f;
        vs1[ni] = (c + 1 < OUT_C) ? __ldg(a_src + c + 1) : 0.f;
        vd0[ni] = (c < OUT_C) ? __ldg(a_dst + c) : 0.f;
        vd1[ni] = (c + 1 < OUT_C) ? __ldg(a_dst + c + 1) : 0.f;
    }

    #pragma unroll
    for (int mi = 0; mi < 4; mi++) {
        int r = bm + wm * 64 + mi * 16 + (lane >> 2);
        #pragma unroll
        for (int ni = 0; ni < 4; ni++) {
            int c = n0 + wn * 32 + ni * 8 + ((lane & 3) << 1);
            if (c >= OUT_C) continue;
            if (r < M)
                *(float2*)(g_h + (size_t)r * OUT_C + c) =
                    make_float2(acc[mi][ni][0], acc[mi][ni][1]);
            if (r + 8 < M)
                *(float2*)(g_h + (size_t)(r + 8) * OUT_C + c) =
                    make_float2(acc[mi][ni][2], acc[mi][ni][3]);
        }
        float ps0 = 0.f, pd0 = 0.f, ps1 = 0.f, pd1 = 0.f;
        #pragma unroll
        for (int ni = 0; ni < 4; ni++) {
            ps0 += acc[mi][ni][0] * vs0[ni] + acc[mi][ni][1] * vs1[ni];
            pd0 += acc[mi][ni][0] * vd0[ni] + acc[mi][ni][1] * vd1[ni];
            ps1 += acc[mi][ni][2] * vs0[ni] + acc[mi][ni][3] * vs1[ni];
            pd1 += acc[mi][ni][2] * vd0[ni] + acc[mi][ni][3] * vd1[ni];
        }
        #pragma unroll
        for (int o = 1; o <= 2; o <<= 1) {
            ps0 += __shfl_xor_sync(0xffffffffu, ps0, o);
            pd0 += __shfl_xor_sync(0xffffffffu, pd0, o);
            ps1 += __shfl_xor_sync(0xffffffffu, ps1, o);
            pd1 += __shfl_xor_sync(0xffffffffu, pd1, o);
        }
        if ((lane & 3) == 0) {
            if (r < M) { atomicAdd(&g_as[r], ps0); atomicAdd(&g_ad[r], pd0); }
            if (r + 8 < M) { atomicAdd(&g_as[r + 8], ps1); atomicAdd(&g_ad[r + 8], pd1); }
        }
    }
}

// ---------------- fused passAB: warp per dst; e + exp + segment sum ----------
__global__ void passAB_kernel(int n) {
    int w = (int)((blockIdx.x * (size_t)blockDim.x + threadIdx.x) >> 5);
    int lane = threadIdx.x & 31;
    if (w >= n) return;
    int off = g_off[w], deg = g_deg[w];
    float ad = __ldg(&g_ad[w]);
    float s = 0.f;
    for (int i = lane; i < deg; i += 32) {
        int src = __ldg(&g_csr_src[off + i]);
        float e = __ldg(&g_as[src]) + ad;
        e = (e > 0.f) ? e : NEG_SLOPE * e;
        float ex = __expf(e);
        g_pair[off + i] = make_int2(src, __float_as_int(ex));
        s += ex;
    }
    #pragma unroll
    for (int o = 16; o; o >>= 1) s += __shfl_xor_sync(0xffffffffu, s, o);
    if (lane == 0) g_s[w] = __frcp_rn(s);
}

// ---------------- passC core: unroll-by-4 gather with MLP=4 ------------------
__device__ __forceinline__ float4 passC_accum(int d, int c, float4 acc) {
    float rs = __ldg(&g_s[d]);
    int off = g_off[d], deg = g_deg[d];
    const float4* h4 = (const float4*)g_h;
    int j = 0;
    for (; j + 4 <= deg; j += 4) {
        int2 p0 = __ldg(&g_pair[off + j]);
        int2 p1 = __ldg(&g_pair[off + j + 1]);
        int2 p2 = __ldg(&g_pair[off + j + 2]);
        int2 p3 = __ldg(&g_pair[off + j + 3]);
        float4 v0 = __ldg(h4 + (size_t)p0.x * (OUT_C / 4) + c);
        float4 v1 = __ldg(h4 + (size_t)p1.x * (OUT_C / 4) + c);
        float4 v2 = __ldg(h4 + (size_t)p2.x * (OUT_C / 4) + c);
        float4 v3 = __ldg(h4 + (size_t)p3.x * (OUT_C / 4) + c);
        float a0 = __int_as_float(p0.y) * rs;
        float a1 = __int_as_float(p1.y) * rs;
        float a2 = __int_as_float(p2.y) * rs;
        float a3 = __int_as_float(p3.y) * rs;
        acc.x = fmaf(a0, v0.x, acc.x); acc.y = fmaf(a0, v0.y, acc.y);
        acc.z = fmaf(a0, v0.z, acc.z); acc.w = fmaf(a0, v0.w, acc.w);
        acc.x = fmaf(a1, v1.x, acc.x); acc.y = fmaf(a1, v1.y, acc.y);
        acc.z = fmaf(a1, v1.z, acc.z); acc.w = fmaf(a1, v1.w, acc.w);
        acc.x = fmaf(a2, v2.x, acc.x); acc.y = fmaf(a2, v2.y, acc.y);
        acc.z = fmaf(a2, v2.z, acc.z); acc.w = fmaf(a2, v2.w, acc.w);
        acc.x = fmaf(a3, v3.x, acc.x); acc.y = fmaf(a3, v3.y, acc.y);
        acc.z = fmaf(a3, v3.z, acc.z); acc.w = fmaf(a3, v3.w, acc.w);
    }
    for (; j < deg; j++) {
        int2 p = __ldg(&g_pair[off + j]);
        float a = __int_as_float(p.y) * rs;
        float4 v = __ldg(h4 + (size_t)p.x * (OUT_C / 4) + c);
        acc.x = fmaf(a, v.x, acc.x); acc.y = fmaf(a, v.y, acc.y);
        acc.z = fmaf(a, v.z, acc.z); acc.w = fmaf(a, v.w, acc.w);
    }
    return acc;
}

// ---------------- passC layer 1: aggregate + bias + relu -> bf16 hi/lo -------
__global__ __launch_bounds__(896)
void passC_bf16_kernel(int n, const float* __restrict__ bias) {
    int t = blockIdx.x * 896 + threadIdx.x;
    int d = t / 56;
    int c = t % 56;
    if (d >= n) return;
    size_t base = (size_t)d * KP1 + c * 4;
    if (c >= 50) {
        *(uint2*)(g_ahi + base) = make_uint2(0, 0);
        *(uint2*)(g_alo + base) = make_uint2(0, 0);
        return;
    }
    float4 acc = __ldg((const float4*)bias + c);
    acc = passC_accum(d, c, acc);
    acc.x = fmaxf(acc.x, 0.f); acc.y = fmaxf(acc.y, 0.f);
    acc.z = fmaxf(acc.z, 0.f); acc.w = fmaxf(acc.w, 0.f);
    uint2 uh, ul;
    split4(acc, uh, ul);
    *(uint2*)(g_ahi + base) = uh;
    *(uint2*)(g_alo + base) = ul;
}

// ---------------- passC layer 2: aggregate + bias + relu -> fp32 out ---------
__global__ __launch_bounds__(800)
void passC_f32_kernel(int n, float* __restrict__ out,
                      const float* __restrict__ bias) {
    int t = blockIdx.x * 800 + threadIdx.x;
    int d = t / 50;
    int c = t % 50;
    if (d >= n) return;
    float4 acc = __ldg((const float4*)bias + c);
    acc = passC_accum(d, c, acc);
    acc.x = fmaxf(acc.x, 0.f); acc.y = fmaxf(acc.y, 0.f);
    acc.z = fmaxf(acc.z, 0.f); acc.w = fmaxf(acc.w, 0.f);
    ((float4*)out)[(size_t)d * (OUT_C / 4) + c] = acc;
}

// ---------------- launch -----------------------------------------------------
extern "C" void kernel_launch(void* const* d_in, const int* in_sizes, int n_in,
                              void* d_out, int out_size) {
    const float* x      = (const float*)d_in[0];
    const float* W0     = (const float*)d_in[1];
    const float* a_src0 = (const float*)d_in[2];
    const float* a_dst0 = (const float*)d_in[3];
    const float* b0     = (const float*)d_in[4];
    const float* W1     = (const float*)d_in[5];
    const float* a_src1 = (const float*)d_in[6];
    const float* a_dst1 = (const float*)d_in[7];
    const float* b1     = (const float*)d_in[8];
    const void*  ei     = d_in[9];

    int n    = in_sizes[0] / IN_C;   // 100000
    int E    = in_sizes[9] / 2;      // 1600000
    int Etot = E + n;

    cudaFuncSetAttribute(gemm_tc_kernel<true>,
                         cudaFuncAttributeMaxDynamicSharedMemorySize, GEMM_SMEM);
    cudaFuncSetAttribute(gemm_tc_kernel<false>,
                         cudaFuncAttributeMaxDynamicSharedMemorySize, GEMM_SMEM);

    dim3 gemm_grid(2, (n + 127) / 128);   // x = n-tile (fast), y = m-tile
    int node_blocks  = (n + 255) / 256;
    int edge_blocks  = (Etot + 511) / 512;
    int scan_blocks  = (n + 1023) / 1024;
    int warp_blocks  = (int)(((long long)n * 32 + 255) / 256);
    int aggC1_blocks = (int)(((long long)n * 56 + 895) / 896);
    int aggC2_blocks = (int)(((long long)n * 50 + 799) / 800);

    // ----- layer 1 front (gemm is 4th launch -> ncu capture) -----
    zero_asad_kernel<<<node_blocks, 256>>>(n);
    probe_kernel<<<1, 32>>>((const int*)ei);
    split_w_kernel<<<(NPAD * KP0 + 255) / 256, 256>>>(W0, IN_C, KP0);
    gemm_tc_kernel<true><<<gemm_grid, 256, GEMM_SMEM>>>(
        n, IN_C, IN_C, KP0, KP0 / 32, x, a_src0, a_dst0);

    // ----- CSR build -----
    zero_deg_kernel<<<node_blocks, 256>>>(n);
    hist_kernel<<<edge_blocks, 512>>>(ei, E, Etot);
    scan1_kernel<<<scan_blocks, 1024>>>(n);
    scan2_kernel<<<1, 128>>>(scan_blocks);
    scan3_kernel<<<node_blocks, 256>>>(n);
    fill_kernel<<<edge_blocks, 512>>>(ei, E, Etot);

    // ----- layer 1 back -----
    passAB_kernel<<<warp_blocks, 256>>>(n);
    passC_bf16_kernel<<<aggC1_blocks, 896>>>(n, b0);

    // ----- layer 2 -----
    zero_asad_kernel<<<node_blocks, 256>>>(n);
    split_w_kernel<<<(NPAD * KP1 + 255) / 256, 256>>>(W1, OUT_C, KP1);
    gemm_tc_kernel<false><<<gemm_grid, 256, GEMM_SMEM>>>(
        n, KP1, OUT_C, KP1, KP1 / 32, nullptr, a_src1, a_dst1);
    passAB_kernel<<<warp_blocks, 256>>>(n);
    passC_f32_kernel<<<aggC2_blocks, 800>>>(n, (float*)d_out, b1);
}